// round 3
// baseline (speedup 1.0000x reference)
#include <cuda_runtime.h>
#include <math.h>

#define NN 50000
#define EE 800000

typedef unsigned long long u64;

// Scratch (static __device__ — allocation-free per harness rules)
__device__ float g_AB[(size_t)NN * 256];   // A | B per node
__device__ float g_num[(size_t)NN * 128];  // segment sum accumulator
__device__ float g_t[(size_t)NN * 128];    // node hidden
__device__ int   g_deg[NN];

__device__ __forceinline__ float silu(float x) {
    return __fdividef(x, 1.0f + __expf(-x));
}

__device__ __forceinline__ u64 pack2(float x) {
    unsigned r = __float_as_uint(x);
    u64 d;
    asm("mov.b64 %0, {%1, %2};" : "=l"(d) : "r"(r), "r"(r));
    return d;
}
__device__ __forceinline__ void fma2(u64 &d, u64 a, u64 b) {
    asm("fma.rn.f32x2 %0, %1, %2, %0;" : "+l"(d) : "l"(a), "l"(b));
}
__device__ __forceinline__ float2 upk(u64 v) {
    unsigned lo, hi;
    asm("mov.b64 {%0, %1}, %2;" : "=r"(lo), "=r"(hi) : "l"(v));
    return make_float2(__uint_as_float(lo), __uint_as_float(hi));
}
__device__ __forceinline__ void red4(float* p, float a, float b, float c, float d) {
    asm volatile("red.global.add.v4.f32 [%0], {%1, %2, %3, %4};"
                 :: "l"(p), "f"(a), "f"(b), "f"(c), "f"(d) : "memory");
}

// Swizzled transposed A-tile store: element (k, r) of [K][64] tile.
// XOR swizzle keeps 8-row groups contiguous while making staging STS conflict-free.
__device__ __forceinline__ void stg_as(float* As, int k, int r, float v) {
    As[k * 64 + (r ^ (((k >> 5) & 7) << 3))] = v;
}

// 64-row x 128-col register-tiled GEMM with f32x2 packed FMA.
// As: [KDIM][64] transposed+swizzled. Wp: W + colg*4 (row stride WS floats).
// acc[rp][c]: row-pair (2rp,2rp+1) packed in f32x2, col c.
template<int KDIM, int WS>
__device__ __forceinline__ void gemm_inner(const float* __restrict__ As,
                                           const float* __restrict__ Wp,
                                           u64 acc[4][4], int rowg) {
    #pragma unroll 4
    for (int k = 0; k < KDIM; k++) {
        const u64* ap = (const u64*)(As + k * 64 + ((rowg ^ ((k >> 5) & 7)) << 3));
        u64 a0 = ap[0], a1 = ap[1], a2 = ap[2], a3 = ap[3];
        float4 b = *(const float4*)(Wp + k * WS);
        u64 b0 = pack2(b.x), b1 = pack2(b.y), b2 = pack2(b.z), b3 = pack2(b.w);
        fma2(acc[0][0], a0, b0); fma2(acc[0][1], a0, b1); fma2(acc[0][2], a0, b2); fma2(acc[0][3], a0, b3);
        fma2(acc[1][0], a1, b0); fma2(acc[1][1], a1, b1); fma2(acc[1][2], a1, b2); fma2(acc[1][3], a1, b3);
        fma2(acc[2][0], a2, b0); fma2(acc[2][1], a2, b1); fma2(acc[2][2], a2, b2); fma2(acc[2][3], a2, b3);
        fma2(acc[3][0], a3, b0); fma2(acc[3][1], a3, b1); fma2(acc[3][2], a3, b2); fma2(acc[3][3], a3, b3);
    }
}

__global__ void k_zero() {
    int i = blockIdx.x * blockDim.x + threadIdx.x;
    int stride = gridDim.x * blockDim.x;
    float4 z = make_float4(0.f, 0.f, 0.f, 0.f);
    for (int j = i; j < NN * 128 / 4; j += stride) ((float4*)g_num)[j] = z;
    for (int j = i; j < NN; j += stride) g_deg[j] = 0;
}

__global__ void k_deg(const int* __restrict__ ei) {
    int i = blockIdx.x * blockDim.x + threadIdx.x;
    int stride = gridDim.x * blockDim.x;
    for (int e = i; e < EE; e += stride) atomicAdd(&g_deg[ei[e]], 1);
}

// ---------------- K1: AB = h @ [We1_top | We1_bot]  ([N,128] -> [N,256]) -------------
__global__ void __launch_bounds__(256, 1) k_pre(const float* __restrict__ h,
                                                const float* __restrict__ We1) {
    extern __shared__ float sm[];
    float* Ws = sm;              // [128][256]
    float* As = sm + 128 * 256;  // [128][64]
    int tid = threadIdx.x;
    for (int idx = tid; idx < 128 * 256; idx += 256) {
        int k = idx >> 8, c = idx & 255;
        Ws[idx] = (c < 128) ? We1[k * 128 + c] : We1[(128 + k) * 128 + (c - 128)];
    }
    int r = tid >> 2, kq = tid & 3;
    int colg = tid & 31, rowg = tid >> 5;
    const int ntiles = (NN + 63) >> 6;
    for (int tile = blockIdx.x; tile < ntiles; tile += gridDim.x) {
        int base = tile << 6;
        __syncthreads();
        int node = base + r;
        if (node < NN) {
            const float4* src = (const float4*)(h + (size_t)node * 128 + kq * 32);
            #pragma unroll
            for (int i4 = 0; i4 < 8; i4++) {
                float4 v = src[i4];
                int k0 = kq * 32 + i4 * 4;
                stg_as(As, k0 + 0, r, v.x); stg_as(As, k0 + 1, r, v.y);
                stg_as(As, k0 + 2, r, v.z); stg_as(As, k0 + 3, r, v.w);
            }
        } else {
            #pragma unroll
            for (int i = 0; i < 32; i++) stg_as(As, kq * 32 + i, r, 0.f);
        }
        __syncthreads();
        #pragma unroll
        for (int half = 0; half < 2; half++) {
            u64 acc[4][4] = {};
            gemm_inner<128, 256>(As, Ws + half * 128 + colg * 4, acc, rowg);
            #pragma unroll
            for (int rp = 0; rp < 4; rp++) {
                float2 c0 = upk(acc[rp][0]), c1 = upk(acc[rp][1]);
                float2 c2 = upk(acc[rp][2]), c3 = upk(acc[rp][3]);
                int r0 = rowg * 8 + rp * 2;
                if (base + r0 < NN)
                    *(float4*)(g_AB + (size_t)(base + r0) * 256 + half * 128 + colg * 4)
                        = make_float4(c0.x, c1.x, c2.x, c3.x);
                if (base + r0 + 1 < NN)
                    *(float4*)(g_AB + (size_t)(base + r0 + 1) * 256 + half * 128 + colg * 4)
                        = make_float4(c0.y, c1.y, c2.y, c3.y);
            }
        }
    }
}

// ---------------- K2: edge kernel — pre = silu(A[row]+B[col]+dist*w+b); m = silu(pre@We2+be2); scatter ----
__global__ void __launch_bounds__(256, 2) k_edge(const float* __restrict__ xz,
        const int* __restrict__ ei, const float* __restrict__ We1,
        const float* __restrict__ be1, const float* __restrict__ We2,
        const float* __restrict__ be2) {
    extern __shared__ float sm[];
    float* Ws   = sm;                       // [128][128] We2
    float* As   = sm + 128 * 128;           // [128][64]
    float* sW1l = sm + 128 * 128 + 128 * 64; // [128] last We1 row
    float* sB1  = sW1l + 128;                // [128] be1
    __shared__ int s_row[64];
    int tid = threadIdx.x;
    for (int idx = tid; idx < 128 * 128; idx += 256) Ws[idx] = We2[idx];
    if (tid < 128) { sW1l[tid] = We1[256 * 128 + tid]; sB1[tid] = be1[tid]; }
    int r = tid >> 2, kq = tid & 3;
    int colg = tid & 31, rowg = tid >> 5;
    float4 be2v = *(const float4*)(be2 + colg * 4);
    const int ntiles = EE >> 6;  // 12500, exact
    for (int tile = blockIdx.x; tile < ntiles; tile += gridDim.x) {
        int base = tile << 6;
        __syncthreads();
        {
            int e = base + r;
            int nr = ei[e], nc = ei[EE + e];
            if (kq == 0) s_row[r] = nr;
            float x0 = xz[nr * 3 + 0], y0 = xz[nr * 3 + 1], z0 = xz[nr * 3 + 2];
            float x1 = xz[nc * 3 + 0], y1 = xz[nc * 3 + 1], z1 = xz[nc * 3 + 2];
            float dx = x0 - x1, dy = y0 - y1, dzz = z0 - z1;
            float u = (dx * dx + dy * dy + dzz * dzz) / (2.f * z0 * z1);
            float dist = acoshf(1.f + u);
            const float4* pa = (const float4*)(g_AB + (size_t)nr * 256 + kq * 32);
            const float4* pb = (const float4*)(g_AB + (size_t)nc * 256 + 128 + kq * 32);
            #pragma unroll
            for (int i4 = 0; i4 < 8; i4++) {
                float4 a = pa[i4], b = pb[i4];
                int k0 = kq * 32 + i4 * 4;
                float4 w  = *(const float4*)(sW1l + k0);
                float4 bb = *(const float4*)(sB1 + k0);
                stg_as(As, k0 + 0, r, silu(a.x + b.x + dist * w.x + bb.x));
                stg_as(As, k0 + 1, r, silu(a.y + b.y + dist * w.y + bb.y));
                stg_as(As, k0 + 2, r, silu(a.z + b.z + dist * w.z + bb.z));
                stg_as(As, k0 + 3, r, silu(a.w + b.w + dist * w.w + bb.w));
            }
        }
        __syncthreads();
        u64 acc[4][4] = {};
        gemm_inner<128, 128>(As, Ws + colg * 4, acc, rowg);
        #pragma unroll
        for (int rp = 0; rp < 4; rp++) {
            float2 c0 = upk(acc[rp][0]), c1 = upk(acc[rp][1]);
            float2 c2 = upk(acc[rp][2]), c3 = upk(acc[rp][3]);
            int r0 = rowg * 8 + rp * 2;
            red4(g_num + (size_t)s_row[r0] * 128 + colg * 4,
                 silu(c0.x + be2v.x), silu(c1.x + be2v.y),
                 silu(c2.x + be2v.z), silu(c3.x + be2v.w));
            red4(g_num + (size_t)s_row[r0 + 1] * 128 + colg * 4,
                 silu(c0.y + be2v.x), silu(c1.y + be2v.y),
                 silu(c2.y + be2v.z), silu(c3.y + be2v.w));
        }
    }
}

// ---------------- K3a: t = silu([h, num/max(deg,1)] @ Wn1 + bn1) -----------------
__global__ void __launch_bounds__(256, 1) k_node1(const float* __restrict__ h,
        const float* __restrict__ Wn1, const float* __restrict__ bn1) {
    extern __shared__ float sm[];
    float* Ws = sm;              // [256][128]
    float* As = sm + 256 * 128;  // [256][64]
    int tid = threadIdx.x;
    for (int idx = tid; idx < 256 * 128; idx += 256) Ws[idx] = Wn1[idx];
    int r = tid >> 2, kq = tid & 3;
    int colg = tid & 31, rowg = tid >> 5;
    float4 bn1v = *(const float4*)(bn1 + colg * 4);
    const int ntiles = (NN + 63) >> 6;
    for (int tile = blockIdx.x; tile < ntiles; tile += gridDim.x) {
        int base = tile << 6;
        __syncthreads();
        int node = base + r;
        if (node < NN) {
            float scale = 1.0f / fmaxf((float)g_deg[node], 1.0f);
            const float4* ph = (const float4*)(h + (size_t)node * 128 + kq * 32);
            const float4* pn = (const float4*)(g_num + (size_t)node * 128 + kq * 32);
            #pragma unroll
            for (int i4 = 0; i4 < 8; i4++) {
                float4 v = ph[i4];
                int k0 = kq * 32 + i4 * 4;
                stg_as(As, k0 + 0, r, v.x); stg_as(As, k0 + 1, r, v.y);
                stg_as(As, k0 + 2, r, v.z); stg_as(As, k0 + 3, r, v.w);
            }
            #pragma unroll
            for (int i4 = 0; i4 < 8; i4++) {
                float4 v = pn[i4];
                int k0 = 128 + kq * 32 + i4 * 4;
                stg_as(As, k0 + 0, r, v.x * scale); stg_as(As, k0 + 1, r, v.y * scale);
                stg_as(As, k0 + 2, r, v.z * scale); stg_as(As, k0 + 3, r, v.w * scale);
            }
        } else {
            #pragma unroll
            for (int i = 0; i < 32; i++) {
                stg_as(As, kq * 32 + i, r, 0.f);
                stg_as(As, 128 + kq * 32 + i, r, 0.f);
            }
        }
        __syncthreads();
        u64 acc[4][4] = {};
        gemm_inner<256, 128>(As, Ws + colg * 4, acc, rowg);
        #pragma unroll
        for (int rp = 0; rp < 4; rp++) {
            float2 c0 = upk(acc[rp][0]), c1 = upk(acc[rp][1]);
            float2 c2 = upk(acc[rp][2]), c3 = upk(acc[rp][3]);
            int r0 = rowg * 8 + rp * 2;
            if (base + r0 < NN)
                *(float4*)(g_t + (size_t)(base + r0) * 128 + colg * 4) =
                    make_float4(silu(c0.x + bn1v.x), silu(c1.x + bn1v.y),
                                silu(c2.x + bn1v.z), silu(c3.x + bn1v.w));
            if (base + r0 + 1 < NN)
                *(float4*)(g_t + (size_t)(base + r0 + 1) * 128 + colg * 4) =
                    make_float4(silu(c0.y + bn1v.x), silu(c1.y + bn1v.y),
                                silu(c2.y + bn1v.z), silu(c3.y + bn1v.w));
        }
    }
}

// ---------------- K3b: out = h + t @ Wn2 + bn2 -----------------
__global__ void __launch_bounds__(256, 2) k_node2(const float* __restrict__ h,
        const float* __restrict__ Wn2, const float* __restrict__ bn2,
        float* __restrict__ out) {
    extern __shared__ float sm[];
    float* Ws = sm;              // [128][128]
    float* As = sm + 128 * 128;  // [128][64]
    int tid = threadIdx.x;
    for (int idx = tid; idx < 128 * 128; idx += 256) Ws[idx] = Wn2[idx];
    int r = tid >> 2, kq = tid & 3;
    int colg = tid & 31, rowg = tid >> 5;
    float4 bn2v = *(const float4*)(bn2 + colg * 4);
    const int ntiles = (NN + 63) >> 6;
    for (int tile = blockIdx.x; tile < ntiles; tile += gridDim.x) {
        int base = tile << 6;
        __syncthreads();
        int node = base + r;
        if (node < NN) {
            const float4* pt = (const float4*)(g_t + (size_t)node * 128 + kq * 32);
            #pragma unroll
            for (int i4 = 0; i4 < 8; i4++) {
                float4 v = pt[i4];
                int k0 = kq * 32 + i4 * 4;
                stg_as(As, k0 + 0, r, v.x); stg_as(As, k0 + 1, r, v.y);
                stg_as(As, k0 + 2, r, v.z); stg_as(As, k0 + 3, r, v.w);
            }
        } else {
            #pragma unroll
            for (int i = 0; i < 32; i++) stg_as(As, kq * 32 + i, r, 0.f);
        }
        __syncthreads();
        u64 acc[4][4] = {};
        gemm_inner<128, 128>(As, Ws + colg * 4, acc, rowg);
        #pragma unroll
        for (int rp = 0; rp < 4; rp++) {
            float2 c0 = upk(acc[rp][0]), c1 = upk(acc[rp][1]);
            float2 c2 = upk(acc[rp][2]), c3 = upk(acc[rp][3]);
            int r0 = rowg * 8 + rp * 2;
            if (base + r0 < NN) {
                float4 hv = *(const float4*)(h + (size_t)(base + r0) * 128 + colg * 4);
                *(float4*)(out + (size_t)(base + r0) * 128 + colg * 4) =
                    make_float4(hv.x + c0.x + bn2v.x, hv.y + c1.x + bn2v.y,
                                hv.z + c2.x + bn2v.z, hv.w + c3.x + bn2v.w);
            }
            if (base + r0 + 1 < NN) {
                float4 hv = *(const float4*)(h + (size_t)(base + r0 + 1) * 128 + colg * 4);
                *(float4*)(out + (size_t)(base + r0 + 1) * 128 + colg * 4) =
                    make_float4(hv.x + c0.y + bn2v.x, hv.y + c1.y + bn2v.y,
                                hv.z + c2.y + bn2v.z, hv.w + c3.y + bn2v.w);
            }
        }
    }
}

extern "C" void kernel_launch(void* const* d_in, const int* in_sizes, int n_in,
                              void* d_out, int out_size) {
    (void)in_sizes; (void)n_in; (void)out_size;
    const float* xz  = (const float*)d_in[0];
    const float* h   = (const float*)d_in[1];
    const float* We1 = (const float*)d_in[2];
    const float* be1 = (const float*)d_in[3];
    const float* We2 = (const float*)d_in[4];
    const float* be2 = (const float*)d_in[5];
    const float* Wn1 = (const float*)d_in[6];
    const float* bn1 = (const float*)d_in[7];
    const float* Wn2 = (const float*)d_in[8];
    const float* bn2 = (const float*)d_in[9];
    const int*   ei  = (const int*)d_in[10];
    float* out = (float*)d_out;

    cudaFuncSetAttribute(k_pre,   cudaFuncAttributeMaxDynamicSharedMemorySize, 163840);
    cudaFuncSetAttribute(k_edge,  cudaFuncAttributeMaxDynamicSharedMemorySize, 99328);
    cudaFuncSetAttribute(k_node1, cudaFuncAttributeMaxDynamicSharedMemorySize, 196608);
    cudaFuncSetAttribute(k_node2, cudaFuncAttributeMaxDynamicSharedMemorySize, 98304);

    k_zero<<<1024, 256>>>();
    k_deg<<<1024, 256>>>(ei);
    k_pre<<<152, 256, 163840>>>(h, We1);
    k_edge<<<304, 256, 99328>>>(xz, ei, We1, be1, We2, be2);
    k_node1<<<152, 256, 196608>>>(h, Wn1, bn1);
    k_node2<<<304, 256, 98304>>>(h, Wn2, bn2, out);
}

// round 6
// speedup vs baseline: 1.4294x; 1.4294x over previous
#include <cuda_runtime.h>
#include <math.h>
#include <stdint.h>

#define NN 50000
#define EE 800000
#define NTIL (EE / 128)   // 6250 tiles of 128 edges

typedef unsigned long long u64;
typedef unsigned int u32;

// Scratch (static __device__ — allocation-free per harness rules)
__device__ float g_AB[(size_t)NN * 256];   // A | B per node
__device__ float g_num[(size_t)NN * 128];  // segment sum accumulator
__device__ float g_t[(size_t)NN * 128];    // node hidden
__device__ int   g_deg[NN];

__device__ __forceinline__ float silu(float x) {
    return __fdividef(x, 1.0f + __expf(-x));
}
// silu via hardware tanh: x*sigmoid(x) = h + h*tanh(h), h = x/2
__device__ __forceinline__ float silu_t(float x) {
    float h = 0.5f * x, t;
    asm("tanh.approx.f32 %0, %1;" : "=f"(t) : "f"(h));
    return h + h * t;
}
__device__ __forceinline__ u32 to_tf32(float x) {
    u32 t; asm("cvt.rna.tf32.f32 %0, %1;" : "=r"(t) : "f"(x)); return t;
}
__device__ __forceinline__ void mma8(float* d, u32 a0, u32 a1, u32 a2, u32 a3,
                                     u32 b0, u32 b1) {
    asm volatile("mma.sync.aligned.m16n8k8.row.col.f32.tf32.tf32.f32 "
        "{%0,%1,%2,%3}, {%4,%5,%6,%7}, {%8,%9}, {%0,%1,%2,%3};"
        : "+f"(d[0]), "+f"(d[1]), "+f"(d[2]), "+f"(d[3])
        : "r"(a0), "r"(a1), "r"(a2), "r"(a3), "r"(b0), "r"(b1));
}

__device__ __forceinline__ u64 pack2(float x) {
    unsigned r = __float_as_uint(x);
    u64 d;
    asm("mov.b64 %0, {%1, %2};" : "=l"(d) : "r"(r), "r"(r));
    return d;
}
__device__ __forceinline__ void fma2(u64 &d, u64 a, u64 b) {
    asm("fma.rn.f32x2 %0, %1, %2, %0;" : "+l"(d) : "l"(a), "l"(b));
}
__device__ __forceinline__ float2 upk(u64 v) {
    unsigned lo, hi;
    asm("mov.b64 {%0, %1}, %2;" : "=r"(lo), "=r"(hi) : "l"(v));
    return make_float2(__uint_as_float(lo), __uint_as_float(hi));
}
__device__ __forceinline__ void red4(float* p, float a, float b, float c, float d) {
    asm volatile("red.global.add.v4.f32 [%0], {%1, %2, %3, %4};"
                 :: "l"(p), "f"(a), "f"(b), "f"(c), "f"(d) : "memory");
}

// ============== fp32 f32x2 GEMM machinery (non-edge kernels, proven) ==============

__device__ __forceinline__ void stg_as(float* As, int k, int r, float v) {
    As[k * 64 + (r ^ (((k >> 5) & 7) << 3))] = v;
}

template<int KDIM, int WS>
__device__ __forceinline__ void gemm_inner(const float* __restrict__ As,
                                           const float* __restrict__ Wp,
                                           u64 acc[4][4], int rowg) {
    #pragma unroll 4
    for (int k = 0; k < KDIM; k++) {
        const u64* ap = (const u64*)(As + k * 64 + ((rowg ^ ((k >> 5) & 7)) << 3));
        u64 a0 = ap[0], a1 = ap[1], a2 = ap[2], a3 = ap[3];
        float4 b = *(const float4*)(Wp + k * WS);
        u64 b0 = pack2(b.x), b1 = pack2(b.y), b2 = pack2(b.z), b3 = pack2(b.w);
        fma2(acc[0][0], a0, b0); fma2(acc[0][1], a0, b1); fma2(acc[0][2], a0, b2); fma2(acc[0][3], a0, b3);
        fma2(acc[1][0], a1, b0); fma2(acc[1][1], a1, b1); fma2(acc[1][2], a1, b2); fma2(acc[1][3], a1, b3);
        fma2(acc[2][0], a2, b0); fma2(acc[2][1], a2, b1); fma2(acc[2][2], a2, b2); fma2(acc[2][3], a2, b3);
        fma2(acc[3][0], a3, b0); fma2(acc[3][1], a3, b1); fma2(acc[3][2], a3, b2); fma2(acc[3][3], a3, b3);
    }
}

__global__ void k_zero() {
    int i = blockIdx.x * blockDim.x + threadIdx.x;
    int stride = gridDim.x * blockDim.x;
    float4 z = make_float4(0.f, 0.f, 0.f, 0.f);
    for (int j = i; j < NN * 128 / 4; j += stride) ((float4*)g_num)[j] = z;
    for (int j = i; j < NN; j += stride) g_deg[j] = 0;
}

__global__ void k_deg(const int* __restrict__ ei) {
    int i = blockIdx.x * blockDim.x + threadIdx.x;
    int stride = gridDim.x * blockDim.x;
    for (int e = i; e < EE; e += stride) atomicAdd(&g_deg[ei[e]], 1);
}

// ---------------- K1: AB = h @ [We1_top | We1_bot] -------------
__global__ void __launch_bounds__(256, 1) k_pre(const float* __restrict__ h,
                                                const float* __restrict__ We1) {
    extern __shared__ float sm[];
    float* Ws = sm;              // [128][256]
    float* As = sm + 128 * 256;  // [128][64]
    int tid = threadIdx.x;
    for (int idx = tid; idx < 128 * 256; idx += 256) {
        int k = idx >> 8, c = idx & 255;
        Ws[idx] = (c < 128) ? We1[k * 128 + c] : We1[(128 + k) * 128 + (c - 128)];
    }
    int r = tid >> 2, kq = tid & 3;
    int colg = tid & 31, rowg = tid >> 5;
    const int ntiles = (NN + 63) >> 6;
    for (int tile = blockIdx.x; tile < ntiles; tile += gridDim.x) {
        int base = tile << 6;
        __syncthreads();
        int node = base + r;
        if (node < NN) {
            const float4* src = (const float4*)(h + (size_t)node * 128 + kq * 32);
            #pragma unroll
            for (int i4 = 0; i4 < 8; i4++) {
                float4 v = src[i4];
                int k0 = kq * 32 + i4 * 4;
                stg_as(As, k0 + 0, r, v.x); stg_as(As, k0 + 1, r, v.y);
                stg_as(As, k0 + 2, r, v.z); stg_as(As, k0 + 3, r, v.w);
            }
        } else {
            #pragma unroll
            for (int i = 0; i < 32; i++) stg_as(As, kq * 32 + i, r, 0.f);
        }
        __syncthreads();
        #pragma unroll
        for (int half = 0; half < 2; half++) {
            u64 acc[4][4] = {};
            gemm_inner<128, 256>(As, Ws + half * 128 + colg * 4, acc, rowg);
            #pragma unroll
            for (int rp = 0; rp < 4; rp++) {
                float2 c0 = upk(acc[rp][0]), c1 = upk(acc[rp][1]);
                float2 c2 = upk(acc[rp][2]), c3 = upk(acc[rp][3]);
                int r0 = rowg * 8 + rp * 2;
                if (base + r0 < NN)
                    *(float4*)(g_AB + (size_t)(base + r0) * 256 + half * 128 + colg * 4)
                        = make_float4(c0.x, c1.x, c2.x, c3.x);
                if (base + r0 + 1 < NN)
                    *(float4*)(g_AB + (size_t)(base + r0 + 1) * 256 + half * 128 + colg * 4)
                        = make_float4(c0.y, c1.y, c2.y, c3.y);
            }
        }
    }
}

// ---------------- K2: tf32 mma.sync edge kernel -----------------
// 512 thr, 1 CTA/SM persistent. smem: A tile [128 edges][128] tf32 (XOR-swizzled
// c' = c ^ ((r&7)<<2)) + resident We2 table [128][128] tf32 (col-permuted for red4
// epilogue, swizzled n' = n ^ ((k&3)<<3)). 16 warps as 4(M)x4(N): warp computes
// M=32 rows x N=32 cols with m16n8k8 tf32 mma. Accumulators stay in registers;
// epilogue = silu + red.global.add.v4 straight from the C-fragments.

__global__ void __launch_bounds__(512, 1) k_edge2(
        const float* __restrict__ xz, const int* __restrict__ ei,
        const float* __restrict__ We1, const float* __restrict__ be1,
        const float* __restrict__ We2, const float* __restrict__ be2) {
    extern __shared__ u32 smu[];
    u32* As = smu;            // 16384 words (64KB)
    u32* Bs = smu + 16384;    // 16384 words (64KB)
    __shared__ int s_row[128];
    __shared__ float sW1l[128], sB1[128];

    int tid = threadIdx.x, wid = tid >> 5, lane = tid & 31;
    int warp_m = wid >> 2, warp_n = wid & 3;
    int q = lane & 3, a8 = lane >> 2;

    // Build B table once: logical-col permutation + swizzle + tf32 convert.
    // phys (nb, c) <- logical pairbase + 4*(c>>1) + 2*(nb&1) + (c&1)
    for (int idx = tid; idx < 16384; idx += 512) {
        int k = idx >> 7, np = idx & 127;
        int nb = np >> 3, c = np & 7;
        int nlog = ((nb >> 1) << 4) + ((c >> 1) << 2) + ((nb & 1) << 1) + (c & 1);
        Bs[k * 128 + (np ^ ((k & 3) << 3))] = to_tf32(We2[k * 128 + nlog]);
    }
    if (tid < 128) { sW1l[tid] = We1[256 * 128 + tid]; sB1[tid] = be1[tid]; }

    // be2 in logical order for the two nb-pairs this thread covers
    float4 bz0 = *(const float4*)(be2 + warp_n * 32 + q * 4);
    float4 bz1 = *(const float4*)(be2 + warp_n * 32 + 16 + q * 4);

    int r = tid >> 2, kq = tid & 3;

    for (int tile = blockIdx.x; tile < NTIL; tile += gridDim.x) {
        __syncthreads();
        // ---- produce A tile: pre = silu(A[row]+B[col]+dist*w1l+b1), tf32 ----
        {
            int e = (tile << 7) + r;
            int nr = ei[e], nc = ei[EE + e];
            if (kq == 0) s_row[r] = nr;
            float x0 = xz[nr * 3 + 0], y0 = xz[nr * 3 + 1], z0 = xz[nr * 3 + 2];
            float x1 = xz[nc * 3 + 0], y1 = xz[nc * 3 + 1], z1 = xz[nc * 3 + 2];
            float dx = x0 - x1, dy = y0 - y1, dz = z0 - z1;
            float u = (dx * dx + dy * dy + dz * dz) / (2.f * z0 * z1);
            float dist = acoshf(1.f + u);
            const float4* pa = (const float4*)(g_AB + (size_t)nr * 256 + kq * 32);
            const float4* pb = (const float4*)(g_AB + (size_t)nc * 256 + 128 + kq * 32);
            int sw = (r & 7) << 2;
            #pragma unroll
            for (int i4 = 0; i4 < 8; i4++) {
                float4 a = pa[i4], b = pb[i4];
                int c0 = kq * 32 + i4 * 4;
                float4 w  = *(const float4*)(sW1l + c0);
                float4 bb = *(const float4*)(sB1 + c0);
                uint4 o;
                o.x = to_tf32(silu_t(a.x + b.x + dist * w.x + bb.x));
                o.y = to_tf32(silu_t(a.y + b.y + dist * w.y + bb.y));
                o.z = to_tf32(silu_t(a.z + b.z + dist * w.z + bb.z));
                o.w = to_tf32(silu_t(a.w + b.w + dist * w.w + bb.w));
                *(uint4*)(As + r * 128 + (c0 ^ sw)) = o;
            }
        }
        __syncthreads();

        // ---- mma: warp covers rows [warp_m*32, +32), cols [warp_n*32, +32) ----
        float acc[2][4][4];
        #pragma unroll
        for (int mt = 0; mt < 2; mt++)
            #pragma unroll
            for (int nb = 0; nb < 4; nb++)
                #pragma unroll
                for (int x = 0; x < 4; x++) acc[mt][nb][x] = 0.f;

        int arow = warp_m * 32;
        #pragma unroll
        for (int ks = 0; ks < 16; ks++) {
            int kk = ks * 8 + q;
            int swn = (kk & 3) << 3;
            u32 bf[4][2];
            #pragma unroll
            for (int nb = 0; nb < 4; nb++) {
                int np = ((warp_n * 4 + nb) << 3) + a8;
                bf[nb][0] = Bs[kk * 128 + (np ^ swn)];
                bf[nb][1] = Bs[(kk + 4) * 128 + (np ^ swn)];
            }
            #pragma unroll
            for (int mt = 0; mt < 2; mt++) {
                int rr = arow + mt * 16 + a8;
                int cc = ks * 8 + q;
                int ca = cc ^ ((rr & 7) << 2);
                u32 a0 = As[rr * 128 + ca];
                u32 a2 = As[rr * 128 + (ca ^ 4)];
                u32 a1 = As[(rr + 8) * 128 + ca];
                u32 a3 = As[(rr + 8) * 128 + (ca ^ 4)];
                #pragma unroll
                for (int nb = 0; nb < 4; nb++)
                    mma8(acc[mt][nb], a0, a1, a2, a3, bf[nb][0], bf[nb][1]);
            }
        }

        // ---- epilogue: m = silu(acc + be2); red4 into g_num[s_row] ----
        #pragma unroll
        for (int mt = 0; mt < 2; mt++) {
            int r0 = arow + mt * 16 + a8;
            int row0 = s_row[r0], row1 = s_row[r0 + 8];
            #pragma unroll
            for (int p = 0; p < 2; p++) {
                float4 bzv = p ? bz1 : bz0;
                float* d0 = g_num + (size_t)row0 * 128 + warp_n * 32 + p * 16 + q * 4;
                float* d1 = g_num + (size_t)row1 * 128 + warp_n * 32 + p * 16 + q * 4;
                int nA = 2 * p, nB = 2 * p + 1;
                red4(d0, silu_t(acc[mt][nA][0] + bzv.x), silu_t(acc[mt][nA][1] + bzv.y),
                         silu_t(acc[mt][nB][0] + bzv.z), silu_t(acc[mt][nB][1] + bzv.w));
                red4(d1, silu_t(acc[mt][nA][2] + bzv.x), silu_t(acc[mt][nA][3] + bzv.y),
                         silu_t(acc[mt][nB][2] + bzv.z), silu_t(acc[mt][nB][3] + bzv.w));
            }
        }
    }
}

// ---------------- K3a: t = silu([h, num/max(deg,1)] @ Wn1 + bn1) -----------------
__global__ void __launch_bounds__(256, 1) k_node1(const float* __restrict__ h,
        const float* __restrict__ Wn1, const float* __restrict__ bn1) {
    extern __shared__ float sm[];
    float* Ws = sm;              // [256][128]
    float* As = sm + 256 * 128;  // [256][64]
    int tid = threadIdx.x;
    for (int idx = tid; idx < 256 * 128; idx += 256) Ws[idx] = Wn1[idx];
    int r = tid >> 2, kq = tid & 3;
    int colg = tid & 31, rowg = tid >> 5;
    float4 bn1v = *(const float4*)(bn1 + colg * 4);
    const int ntiles = (NN + 63) >> 6;
    for (int tile = blockIdx.x; tile < ntiles; tile += gridDim.x) {
        int base = tile << 6;
        __syncthreads();
        int node = base + r;
        if (node < NN) {
            float scale = 1.0f / fmaxf((float)g_deg[node], 1.0f);
            const float4* ph = (const float4*)(h + (size_t)node * 128 + kq * 32);
            const float4* pn = (const float4*)(g_num + (size_t)node * 128 + kq * 32);
            #pragma unroll
            for (int i4 = 0; i4 < 8; i4++) {
                float4 v = ph[i4];
                int k0 = kq * 32 + i4 * 4;
                stg_as(As, k0 + 0, r, v.x); stg_as(As, k0 + 1, r, v.y);
                stg_as(As, k0 + 2, r, v.z); stg_as(As, k0 + 3, r, v.w);
            }
            #pragma unroll
            for (int i4 = 0; i4 < 8; i4++) {
                float4 v = pn[i4];
                int k0 = 128 + kq * 32 + i4 * 4;
                stg_as(As, k0 + 0, r, v.x * scale); stg_as(As, k0 + 1, r, v.y * scale);
                stg_as(As, k0 + 2, r, v.z * scale); stg_as(As, k0 + 3, r, v.w * scale);
            }
        } else {
            #pragma unroll
            for (int i = 0; i < 32; i++) {
                stg_as(As, kq * 32 + i, r, 0.f);
                stg_as(As, 128 + kq * 32 + i, r, 0.f);
            }
        }
        __syncthreads();
        u64 acc[4][4] = {};
        gemm_inner<256, 128>(As, Ws + colg * 4, acc, rowg);
        #pragma unroll
        for (int rp = 0; rp < 4; rp++) {
            float2 c0 = upk(acc[rp][0]), c1 = upk(acc[rp][1]);
            float2 c2 = upk(acc[rp][2]), c3 = upk(acc[rp][3]);
            int r0 = rowg * 8 + rp * 2;
            if (base + r0 < NN)
                *(float4*)(g_t + (size_t)(base + r0) * 128 + colg * 4) =
                    make_float4(silu(c0.x + bn1v.x), silu(c1.x + bn1v.y),
                                silu(c2.x + bn1v.z), silu(c3.x + bn1v.w));
            if (base + r0 + 1 < NN)
                *(float4*)(g_t + (size_t)(base + r0 + 1) * 128 + colg * 4) =
                    make_float4(silu(c0.y + bn1v.x), silu(c1.y + bn1v.y),
                                silu(c2.y + bn1v.z), silu(c3.y + bn1v.w));
        }
    }
}

// ---------------- K3b: out = h + t @ Wn2 + bn2 -----------------
__global__ void __launch_bounds__(256, 2) k_node2(const float* __restrict__ h,
        const float* __restrict__ Wn2, const float* __restrict__ bn2,
        float* __restrict__ out) {
    extern __shared__ float sm[];
    float* Ws = sm;              // [128][128]
    float* As = sm + 128 * 128;  // [128][64]
    int tid = threadIdx.x;
    for (int idx = tid; idx < 128 * 128; idx += 256) Ws[idx] = Wn2[idx];
    int r = tid >> 2, kq = tid & 3;
    int colg = tid & 31, rowg = tid >> 5;
    float4 bn2v = *(const float4*)(bn2 + colg * 4);
    const int ntiles = (NN + 63) >> 6;
    for (int tile = blockIdx.x; tile < ntiles; tile += gridDim.x) {
        int base = tile << 6;
        __syncthreads();
        int node = base + r;
        if (node < NN) {
            const float4* pt = (const float4*)(g_t + (size_t)node * 128 + kq * 32);
            #pragma unroll
            for (int i4 = 0; i4 < 8; i4++) {
                float4 v = pt[i4];
                int k0 = kq * 32 + i4 * 4;
                stg_as(As, k0 + 0, r, v.x); stg_as(As, k0 + 1, r, v.y);
                stg_as(As, k0 + 2, r, v.z); stg_as(As, k0 + 3, r, v.w);
            }
        } else {
            #pragma unroll
            for (int i = 0; i < 32; i++) stg_as(As, kq * 32 + i, r, 0.f);
        }
        __syncthreads();
        u64 acc[4][4] = {};
        gemm_inner<128, 128>(As, Ws + colg * 4, acc, rowg);
        #pragma unroll
        for (int rp = 0; rp < 4; rp++) {
            float2 c0 = upk(acc[rp][0]), c1 = upk(acc[rp][1]);
            float2 c2 = upk(acc[rp][2]), c3 = upk(acc[rp][3]);
            int r0 = rowg * 8 + rp * 2;
            if (base + r0 < NN) {
                float4 hv = *(const float4*)(h + (size_t)(base + r0) * 128 + colg * 4);
                *(float4*)(out + (size_t)(base + r0) * 128 + colg * 4) =
                    make_float4(hv.x + c0.x + bn2v.x, hv.y + c1.x + bn2v.y,
                                hv.z + c2.x + bn2v.z, hv.w + c3.x + bn2v.w);
            }
            if (base + r0 + 1 < NN) {
                float4 hv = *(const float4*)(h + (size_t)(base + r0 + 1) * 128 + colg * 4);
                *(float4*)(out + (size_t)(base + r0 + 1) * 128 + colg * 4) =
                    make_float4(hv.x + c0.y + bn2v.x, hv.y + c1.y + bn2v.y,
                                hv.z + c2.y + bn2v.z, hv.w + c3.y + bn2v.w);
            }
        }
    }
}

extern "C" void kernel_launch(void* const* d_in, const int* in_sizes, int n_in,
                              void* d_out, int out_size) {
    (void)in_sizes; (void)n_in; (void)out_size;
    const float* xz  = (const float*)d_in[0];
    const float* h   = (const float*)d_in[1];
    const float* We1 = (const float*)d_in[2];
    const float* be1 = (const float*)d_in[3];
    const float* We2 = (const float*)d_in[4];
    const float* be2 = (const float*)d_in[5];
    const float* Wn1 = (const float*)d_in[6];
    const float* bn1 = (const float*)d_in[7];
    const float* Wn2 = (const float*)d_in[8];
    const float* bn2 = (const float*)d_in[9];
    const int*   ei  = (const int*)d_in[10];
    float* out = (float*)d_out;

    cudaFuncSetAttribute(k_pre,   cudaFuncAttributeMaxDynamicSharedMemorySize, 163840);
    cudaFuncSetAttribute(k_edge2, cudaFuncAttributeMaxDynamicSharedMemorySize, 131072);
    cudaFuncSetAttribute(k_node1, cudaFuncAttributeMaxDynamicSharedMemorySize, 196608);
    cudaFuncSetAttribute(k_node2, cudaFuncAttributeMaxDynamicSharedMemorySize, 98304);

    k_zero<<<1024, 256>>>();
    k_deg<<<1024, 256>>>(ei);
    k_pre<<<152, 256, 163840>>>(h, We1);
    k_edge2<<<152, 512, 131072>>>(xz, ei, We1, be1, We2, be2);
    k_node1<<<152, 256, 196608>>>(h, Wn1, bn1);
    k_node2<<<304, 256, 98304>>>(h, Wn2, bn2, out);
}

// round 8
// speedup vs baseline: 1.6549x; 1.1577x over previous
#include <cuda_runtime.h>
#include <cuda_bf16.h>
#include <math.h>
#include <stdint.h>

#define NN 50000
#define EE 800000
#define NTIL (EE / 128)        // 6250 tiles of 128 edges
#define NBLK ((NN + 255) / 256) // 196

typedef unsigned long long u64;
typedef unsigned int u32;

// Scratch (static __device__ — allocation-free per harness rules)
__device__ float g_AB[(size_t)NN * 256];   // A | B per node
__device__ float g_num[(size_t)NN * 128];  // segment sum accumulator
__device__ float g_t[(size_t)NN * 128];    // node hidden
__device__ int   g_deg[NN];
__device__ int   g_cur[NN];                // scatter cursors
__device__ int   g_bsum[256], g_bpre[256]; // scan partials
__device__ u64   g_edges[EE];              // sorted (col<<32 | row)

__device__ __forceinline__ float silu(float x) {
    return __fdividef(x, 1.0f + __expf(-x));
}
// silu via hardware tanh: x*sigmoid(x) = h + h*tanh(h), h = x/2
__device__ __forceinline__ float silu_t(float x) {
    float h = 0.5f * x, t;
    asm("tanh.approx.f32 %0, %1;" : "=f"(t) : "f"(h));
    return h + h * t;
}
__device__ __forceinline__ u32 bf2(float lo, float hi) {
    __nv_bfloat162 t = __float22bfloat162_rn(make_float2(lo, hi));
    return *(u32*)&t;
}
__device__ __forceinline__ void mma16(float* d, u32 a0, u32 a1, u32 a2, u32 a3,
                                      u32 b0, u32 b1) {
    asm volatile("mma.sync.aligned.m16n8k16.row.col.f32.bf16.bf16.f32 "
        "{%0,%1,%2,%3}, {%4,%5,%6,%7}, {%8,%9}, {%0,%1,%2,%3};"
        : "+f"(d[0]), "+f"(d[1]), "+f"(d[2]), "+f"(d[3])
        : "r"(a0), "r"(a1), "r"(a2), "r"(a3), "r"(b0), "r"(b1));
}

__device__ __forceinline__ u64 pack2(float x) {
    unsigned r = __float_as_uint(x);
    u64 d;
    asm("mov.b64 %0, {%1, %2};" : "=l"(d) : "r"(r), "r"(r));
    return d;
}
__device__ __forceinline__ void fma2(u64 &d, u64 a, u64 b) {
    asm("fma.rn.f32x2 %0, %1, %2, %0;" : "+l"(d) : "l"(a), "l"(b));
}
__device__ __forceinline__ float2 upk(u64 v) {
    unsigned lo, hi;
    asm("mov.b64 {%0, %1}, %2;" : "=r"(lo), "=r"(hi) : "l"(v));
    return make_float2(__uint_as_float(lo), __uint_as_float(hi));
}
__device__ __forceinline__ void red4(float* p, float a, float b, float c, float d) {
    asm volatile("red.global.add.v4.f32 [%0], {%1, %2, %3, %4};"
                 :: "l"(p), "f"(a), "f"(b), "f"(c), "f"(d) : "memory");
}

// ============== fp32 f32x2 GEMM machinery (non-edge kernels, proven) ==============

__device__ __forceinline__ void stg_as(float* As, int k, int r, float v) {
    As[k * 64 + (r ^ (((k >> 5) & 7) << 3))] = v;
}

template<int KDIM, int WS>
__device__ __forceinline__ void gemm_inner(const float* __restrict__ As,
                                           const float* __restrict__ Wp,
                                           u64 acc[4][4], int rowg) {
    #pragma unroll 4
    for (int k = 0; k < KDIM; k++) {
        const u64* ap = (const u64*)(As + k * 64 + ((rowg ^ ((k >> 5) & 7)) << 3));
        u64 a0 = ap[0], a1 = ap[1], a2 = ap[2], a3 = ap[3];
        float4 b = *(const float4*)(Wp + k * WS);
        u64 b0 = pack2(b.x), b1 = pack2(b.y), b2 = pack2(b.z), b3 = pack2(b.w);
        fma2(acc[0][0], a0, b0); fma2(acc[0][1], a0, b1); fma2(acc[0][2], a0, b2); fma2(acc[0][3], a0, b3);
        fma2(acc[1][0], a1, b0); fma2(acc[1][1], a1, b1); fma2(acc[1][2], a1, b2); fma2(acc[1][3], a1, b3);
        fma2(acc[2][0], a2, b0); fma2(acc[2][1], a2, b1); fma2(acc[2][2], a2, b2); fma2(acc[2][3], a2, b3);
        fma2(acc[3][0], a3, b0); fma2(acc[3][1], a3, b1); fma2(acc[3][2], a3, b2); fma2(acc[3][3], a3, b3);
    }
}

__global__ void k_zero() {
    int i = blockIdx.x * blockDim.x + threadIdx.x;
    int stride = gridDim.x * blockDim.x;
    float4 z = make_float4(0.f, 0.f, 0.f, 0.f);
    for (int j = i; j < NN * 128 / 4; j += stride) ((float4*)g_num)[j] = z;
    for (int j = i; j < NN; j += stride) g_deg[j] = 0;
}

__global__ void k_deg(const int* __restrict__ ei) {
    int i = blockIdx.x * blockDim.x + threadIdx.x;
    int stride = gridDim.x * blockDim.x;
    for (int e = i; e < EE; e += stride) atomicAdd(&g_deg[ei[e]], 1);
}

// -------- counting-sort scan (3 small kernels) + scatter --------
__global__ void k_bsum() {
    __shared__ int s[256];
    int b = blockIdx.x, tid = threadIdx.x, i = b * 256 + tid;
    s[tid] = (i < NN) ? g_deg[i] : 0;
    __syncthreads();
    for (int off = 128; off; off >>= 1) {
        if (tid < off) s[tid] += s[tid + off];
        __syncthreads();
    }
    if (!tid) g_bsum[b] = s[0];
}
__global__ void k_sscan() {
    __shared__ int s[256];
    int tid = threadIdx.x;
    int v0 = (tid < NBLK) ? g_bsum[tid] : 0;
    s[tid] = v0;
    __syncthreads();
    for (int off = 1; off < 256; off <<= 1) {
        int v = (tid >= off) ? s[tid - off] : 0;
        __syncthreads();
        s[tid] += v;
        __syncthreads();
    }
    if (tid < NBLK) g_bpre[tid] = s[tid] - v0;
}
__global__ void k_wcur() {
    __shared__ int s[256];
    int b = blockIdx.x, tid = threadIdx.x, i = b * 256 + tid;
    int d = (i < NN) ? g_deg[i] : 0;
    s[tid] = d;
    __syncthreads();
    for (int off = 1; off < 256; off <<= 1) {
        int v = (tid >= off) ? s[tid - off] : 0;
        __syncthreads();
        s[tid] += v;
        __syncthreads();
    }
    if (i < NN) g_cur[i] = s[tid] - d + g_bpre[b];
}
__global__ void k_scatter(const int* __restrict__ ei) {
    int i = blockIdx.x * blockDim.x + threadIdx.x;
    int stride = gridDim.x * blockDim.x;
    for (int e = i; e < EE; e += stride) {
        int r = ei[e], c = ei[EE + e];
        int pos = atomicAdd(&g_cur[r], 1);
        g_edges[pos] = ((u64)(u32)c << 32) | (u32)r;
    }
}

// ---------------- K1: AB = h @ [We1_top | We1_bot] -------------
__global__ void __launch_bounds__(256, 1) k_pre(const float* __restrict__ h,
                                                const float* __restrict__ We1) {
    extern __shared__ float sm[];
    float* Ws = sm;              // [128][256]
    float* As = sm + 128 * 256;  // [128][64]
    int tid = threadIdx.x;
    for (int idx = tid; idx < 128 * 256; idx += 256) {
        int k = idx >> 8, c = idx & 255;
        Ws[idx] = (c < 128) ? We1[k * 128 + c] : We1[(128 + k) * 128 + (c - 128)];
    }
    int r = tid >> 2, kq = tid & 3;
    int colg = tid & 31, rowg = tid >> 5;
    const int ntiles = (NN + 63) >> 6;
    for (int tile = blockIdx.x; tile < ntiles; tile += gridDim.x) {
        int base = tile << 6;
        __syncthreads();
        int node = base + r;
        if (node < NN) {
            const float4* src = (const float4*)(h + (size_t)node * 128 + kq * 32);
            #pragma unroll
            for (int i4 = 0; i4 < 8; i4++) {
                float4 v = src[i4];
                int k0 = kq * 32 + i4 * 4;
                stg_as(As, k0 + 0, r, v.x); stg_as(As, k0 + 1, r, v.y);
                stg_as(As, k0 + 2, r, v.z); stg_as(As, k0 + 3, r, v.w);
            }
        } else {
            #pragma unroll
            for (int i = 0; i < 32; i++) stg_as(As, kq * 32 + i, r, 0.f);
        }
        __syncthreads();
        #pragma unroll
        for (int half = 0; half < 2; half++) {
            u64 acc[4][4] = {};
            gemm_inner<128, 256>(As, Ws + half * 128 + colg * 4, acc, rowg);
            #pragma unroll
            for (int rp = 0; rp < 4; rp++) {
                float2 c0 = upk(acc[rp][0]), c1 = upk(acc[rp][1]);
                float2 c2 = upk(acc[rp][2]), c3 = upk(acc[rp][3]);
                int r0 = rowg * 8 + rp * 2;
                if (base + r0 < NN)
                    *(float4*)(g_AB + (size_t)(base + r0) * 256 + half * 128 + colg * 4)
                        = make_float4(c0.x, c1.x, c2.x, c3.x);
                if (base + r0 + 1 < NN)
                    *(float4*)(g_AB + (size_t)(base + r0 + 1) * 256 + half * 128 + colg * 4)
                        = make_float4(c0.y, c1.y, c2.y, c3.y);
            }
        }
    }
}

// ---------------- K2: bf16 mma edge kernel, sorted edges, smem reduction ----------
// smem: Bs [128n][64 kpairs] bf16 (32KB), As [128r][64 kpairs] bf16 (32KB),
//       Cs [128][132] f32 staging (66KB). XOR swizzle w ^= (row&7)<<2.
// Per 128-edge tile: gather+silu -> As (bf16), 16 warps (4Mx4N) m16n8k16 MMA,
// store C frags to Cs, then segmented reduction over sorted dests -> few red4.

__global__ void __launch_bounds__(512, 1) k_edge3(
        const float* __restrict__ xz,
        const float* __restrict__ We1, const float* __restrict__ be1,
        const float* __restrict__ We2, const float* __restrict__ be2) {
    extern __shared__ u32 smu[];
    u32* Bs = smu;             // 8192 words
    u32* As = smu + 8192;      // 8192 words
    float* Cs = (float*)(smu + 16384);  // 128*132 floats
    __shared__ int s_row[128];
    __shared__ float sW1l[128], sB1[128];

    int tid = threadIdx.x, wid = tid >> 5, lane = tid & 31;
    int warp_m = wid >> 2, warp_n = wid & 3;
    int q = lane & 3, a8 = lane >> 2;

    // Build bf16 B table: Bs[n][w] = (We2[2w][n], We2[2w+1][n]), swizzled
    for (int idx = tid; idx < 8192; idx += 512) {
        int n = idx >> 6, w = idx & 63;
        Bs[n * 64 + (w ^ ((n & 7) << 2))] =
            bf2(We2[(2 * w) * 128 + n], We2[(2 * w + 1) * 128 + n]);
    }
    if (tid < 128) { sW1l[tid] = We1[256 * 128 + tid]; sB1[tid] = be1[tid]; }

    int r = tid >> 2, kq = tid & 3;
    // reduce-pass constants: lane = column quad, warp = 8-row group
    float4 be2v = *(const float4*)(be2 + lane * 4);

    for (int tile = blockIdx.x; tile < NTIL; tile += gridDim.x) {
        __syncthreads();   // Cs/s_row from previous iteration fully consumed
        // ---- producer: pre = silu(A[row]+B[col]+dist*w1l+b1) -> bf16 As ----
        {
            u64 pr = g_edges[(tile << 7) + r];
            int nr = (int)(u32)pr, nc = (int)(u32)(pr >> 32);
            if (kq == 0) s_row[r] = nr;
            float x0 = xz[nr * 3 + 0], y0 = xz[nr * 3 + 1], z0 = xz[nr * 3 + 2];
            float x1 = xz[nc * 3 + 0], y1 = xz[nc * 3 + 1], z1 = xz[nc * 3 + 2];
            float dx = x0 - x1, dy = y0 - y1, dz = z0 - z1;
            float u = (dx * dx + dy * dy + dz * dz) / (2.f * z0 * z1);
            float dist = acoshf(1.f + u);
            const float4* pa = (const float4*)(g_AB + (size_t)nr * 256 + kq * 32);
            const float4* pb = (const float4*)(g_AB + (size_t)nc * 256 + 128 + kq * 32);
            int sw = (r & 7) << 2;
            #pragma unroll
            for (int j = 0; j < 4; j++) {        // 2 float4s -> one uint4 (8 bf16)
                uint4 o;
                {
                    float4 a = pa[2 * j], b = pb[2 * j];
                    int c0 = kq * 32 + 8 * j;
                    float4 w  = *(const float4*)(sW1l + c0);
                    float4 bb = *(const float4*)(sB1 + c0);
                    float v0 = silu_t(a.x + b.x + dist * w.x + bb.x);
                    float v1 = silu_t(a.y + b.y + dist * w.y + bb.y);
                    float v2 = silu_t(a.z + b.z + dist * w.z + bb.z);
                    float v3 = silu_t(a.w + b.w + dist * w.w + bb.w);
                    o.x = bf2(v0, v1); o.y = bf2(v2, v3);
                }
                {
                    float4 a = pa[2 * j + 1], b = pb[2 * j + 1];
                    int c0 = kq * 32 + 8 * j + 4;
                    float4 w  = *(const float4*)(sW1l + c0);
                    float4 bb = *(const float4*)(sB1 + c0);
                    float v0 = silu_t(a.x + b.x + dist * w.x + bb.x);
                    float v1 = silu_t(a.y + b.y + dist * w.y + bb.y);
                    float v2 = silu_t(a.z + b.z + dist * w.z + bb.z);
                    float v3 = silu_t(a.w + b.w + dist * w.w + bb.w);
                    o.z = bf2(v0, v1); o.w = bf2(v2, v3);
                }
                int w0 = kq * 16 + 4 * j;        // 4-word aligned, swizzle-safe
                *(uint4*)(As + r * 64 + (w0 ^ sw)) = o;
            }
        }
        __syncthreads();

        // ---- MMA: warp (warp_m, warp_n) -> rows warp_m*32+, cols warp_n*32+ ----
        float acc[2][4][4];
        #pragma unroll
        for (int mt = 0; mt < 2; mt++)
            #pragma unroll
            for (int nb = 0; nb < 4; nb++)
                #pragma unroll
                for (int x = 0; x < 4; x++) acc[mt][nb][x] = 0.f;

        int arow = warp_m * 32;
        #pragma unroll
        for (int ks = 0; ks < 8; ks++) {
            u32 bf0[4], bf1[4];
            #pragma unroll
            for (int nb = 0; nb < 4; nb++) {
                int n = warp_n * 32 + nb * 8 + a8;
                int sw = (n & 7) << 2;
                bf0[nb] = Bs[n * 64 + ((ks * 8 + q) ^ sw)];
                bf1[nb] = Bs[n * 64 + ((ks * 8 + q + 4) ^ sw)];
            }
            #pragma unroll
            for (int mt = 0; mt < 2; mt++) {
                int r0 = arow + mt * 16 + a8;
                int sw = (r0 & 7) << 2;
                u32 a0 = As[r0 * 64 + ((ks * 8 + q) ^ sw)];
                u32 a1 = As[(r0 + 8) * 64 + ((ks * 8 + q) ^ sw)];
                u32 a2 = As[r0 * 64 + ((ks * 8 + q + 4) ^ sw)];
                u32 a3 = As[(r0 + 8) * 64 + ((ks * 8 + q + 4) ^ sw)];
                #pragma unroll
                for (int nb = 0; nb < 4; nb++)
                    mma16(acc[mt][nb], a0, a1, a2, a3, bf0[nb], bf1[nb]);
            }
        }

        // ---- stage C fragments to Cs (stride 132) ----
        #pragma unroll
        for (int mt = 0; mt < 2; mt++) {
            int r0 = arow + mt * 16 + a8;
            #pragma unroll
            for (int nb = 0; nb < 4; nb++) {
                int c = warp_n * 32 + nb * 8 + 2 * q;
                *(float2*)(Cs + r0 * 132 + c) = make_float2(acc[mt][nb][0], acc[mt][nb][1]);
                *(float2*)(Cs + (r0 + 8) * 132 + c) = make_float2(acc[mt][nb][2], acc[mt][nb][3]);
            }
        }
        __syncthreads();

        // ---- segmented reduction: warp = rows [wid*8, wid*8+8), lane = col quad ----
        {
            int rb = wid * 8;
            int cur = s_row[rb];
            float4 sum;
            {
                float4 c = *(const float4*)(Cs + rb * 132 + lane * 4);
                sum.x = silu_t(c.x + be2v.x); sum.y = silu_t(c.y + be2v.y);
                sum.z = silu_t(c.z + be2v.z); sum.w = silu_t(c.w + be2v.w);
            }
            #pragma unroll
            for (int i = 1; i < 8; i++) {
                int rr = rb + i;
                int dest = s_row[rr];
                float4 c = *(const float4*)(Cs + rr * 132 + lane * 4);
                float4 v;
                v.x = silu_t(c.x + be2v.x); v.y = silu_t(c.y + be2v.y);
                v.z = silu_t(c.z + be2v.z); v.w = silu_t(c.w + be2v.w);
                if (dest != cur) {
                    red4(g_num + (size_t)cur * 128 + lane * 4, sum.x, sum.y, sum.z, sum.w);
                    sum = v; cur = dest;
                } else {
                    sum.x += v.x; sum.y += v.y; sum.z += v.z; sum.w += v.w;
                }
            }
            red4(g_num + (size_t)cur * 128 + lane * 4, sum.x, sum.y, sum.z, sum.w);
        }
    }
}

// ---------------- K3a: t = silu([h, num/max(deg,1)] @ Wn1 + bn1) -----------------
__global__ void __launch_bounds__(256, 1) k_node1(const float* __restrict__ h,
        const float* __restrict__ Wn1, const float* __restrict__ bn1) {
    extern __shared__ float sm[];
    float* Ws = sm;              // [256][128]
    float* As = sm + 256 * 128;  // [256][64]
    int tid = threadIdx.x;
    for (int idx = tid; idx < 256 * 128; idx += 256) Ws[idx] = Wn1[idx];
    int r = tid >> 2, kq = tid & 3;
    int colg = tid & 31, rowg = tid >> 5;
    float4 bn1v = *(const float4*)(bn1 + colg * 4);
    const int ntiles = (NN + 63) >> 6;
    for (int tile = blockIdx.x; tile < ntiles; tile += gridDim.x) {
        int base = tile << 6;
        __syncthreads();
        int node = base + r;
        if (node < NN) {
            float scale = 1.0f / fmaxf((float)g_deg[node], 1.0f);
            const float4* ph = (const float4*)(h + (size_t)node * 128 + kq * 32);
            const float4* pn = (const float4*)(g_num + (size_t)node * 128 + kq * 32);
            #pragma unroll
            for (int i4 = 0; i4 < 8; i4++) {
                float4 v = ph[i4];
                int k0 = kq * 32 + i4 * 4;
                stg_as(As, k0 + 0, r, v.x); stg_as(As, k0 + 1, r, v.y);
                stg_as(As, k0 + 2, r, v.z); stg_as(As, k0 + 3, r, v.w);
            }
            #pragma unroll
            for (int i4 = 0; i4 < 8; i4++) {
                float4 v = pn[i4];
                int k0 = 128 + kq * 32 + i4 * 4;
                stg_as(As, k0 + 0, r, v.x * scale); stg_as(As, k0 + 1, r, v.y * scale);
                stg_as(As, k0 + 2, r, v.z * scale); stg_as(As, k0 + 3, r, v.w * scale);
            }
        } else {
            #pragma unroll
            for (int i = 0; i < 32; i++) {
                stg_as(As, kq * 32 + i, r, 0.f);
                stg_as(As, 128 + kq * 32 + i, r, 0.f);
            }
        }
        __syncthreads();
        u64 acc[4][4] = {};
        gemm_inner<256, 128>(As, Ws + colg * 4, acc, rowg);
        #pragma unroll
        for (int rp = 0; rp < 4; rp++) {
            float2 c0 = upk(acc[rp][0]), c1 = upk(acc[rp][1]);
            float2 c2 = upk(acc[rp][2]), c3 = upk(acc[rp][3]);
            int r0 = rowg * 8 + rp * 2;
            if (base + r0 < NN)
                *(float4*)(g_t + (size_t)(base + r0) * 128 + colg * 4) =
                    make_float4(silu(c0.x + bn1v.x), silu(c1.x + bn1v.y),
                                silu(c2.x + bn1v.z), silu(c3.x + bn1v.w));
            if (base + r0 + 1 < NN)
                *(float4*)(g_t + (size_t)(base + r0 + 1) * 128 + colg * 4) =
                    make_float4(silu(c0.y + bn1v.x), silu(c1.y + bn1v.y),
                                silu(c2.y + bn1v.z), silu(c3.y + bn1v.w));
        }
    }
}

// ---------------- K3b: out = h + t @ Wn2 + bn2 -----------------
__global__ void __launch_bounds__(256, 2) k_node2(const float* __restrict__ h,
        const float* __restrict__ Wn2, const float* __restrict__ bn2,
        float* __restrict__ out) {
    extern __shared__ float sm[];
    float* Ws = sm;              // [128][128]
    float* As = sm + 128 * 128;  // [128][64]
    int tid = threadIdx.x;
    for (int idx = tid; idx < 128 * 128; idx += 256) Ws[idx] = Wn2[idx];
    int r = tid >> 2, kq = tid & 3;
    int colg = tid & 31, rowg = tid >> 5;
    float4 bn2v = *(const float4*)(bn2 + colg * 4);
    const int ntiles = (NN + 63) >> 6;
    for (int tile = blockIdx.x; tile < ntiles; tile += gridDim.x) {
        int base = tile << 6;
        __syncthreads();
        int node = base + r;
        if (node < NN) {
            const float4* pt = (const float4*)(g_t + (size_t)node * 128 + kq * 32);
            #pragma unroll
            for (int i4 = 0; i4 < 8; i4++) {
                float4 v = pt[i4];
                int k0 = kq * 32 + i4 * 4;
                stg_as(As, k0 + 0, r, v.x); stg_as(As, k0 + 1, r, v.y);
                stg_as(As, k0 + 2, r, v.z); stg_as(As, k0 + 3, r, v.w);
            }
        } else {
            #pragma unroll
            for (int i = 0; i < 32; i++) stg_as(As, kq * 32 + i, r, 0.f);
        }
        __syncthreads();
        u64 acc[4][4] = {};
        gemm_inner<128, 128>(As, Ws + colg * 4, acc, rowg);
        #pragma unroll
        for (int rp = 0; rp < 4; rp++) {
            float2 c0 = upk(acc[rp][0]), c1 = upk(acc[rp][1]);
            float2 c2 = upk(acc[rp][2]), c3 = upk(acc[rp][3]);
            int r0 = rowg * 8 + rp * 2;
            if (base + r0 < NN) {
                float4 hv = *(const float4*)(h + (size_t)(base + r0) * 128 + colg * 4);
                *(float4*)(out + (size_t)(base + r0) * 128 + colg * 4) =
                    make_float4(hv.x + c0.x + bn2v.x, hv.y + c1.x + bn2v.y,
                                hv.z + c2.x + bn2v.z, hv.w + c3.x + bn2v.w);
            }
            if (base + r0 + 1 < NN) {
                float4 hv = *(const float4*)(h + (size_t)(base + r0 + 1) * 128 + colg * 4);
                *(float4*)(out + (size_t)(base + r0 + 1) * 128 + colg * 4) =
                    make_float4(hv.x + c0.y + bn2v.x, hv.y + c1.y + bn2v.y,
                                hv.z + c2.y + bn2v.z, hv.w + c3.y + bn2v.w);
            }
        }
    }
}

extern "C" void kernel_launch(void* const* d_in, const int* in_sizes, int n_in,
                              void* d_out, int out_size) {
    (void)in_sizes; (void)n_in; (void)out_size;
    const float* xz  = (const float*)d_in[0];
    const float* h   = (const float*)d_in[1];
    const float* We1 = (const float*)d_in[2];
    const float* be1 = (const float*)d_in[3];
    const float* We2 = (const float*)d_in[4];
    const float* be2 = (const float*)d_in[5];
    const float* Wn1 = (const float*)d_in[6];
    const float* bn1 = (const float*)d_in[7];
    const float* Wn2 = (const float*)d_in[8];
    const float* bn2 = (const float*)d_in[9];
    const int*   ei  = (const int*)d_in[10];
    float* out = (float*)d_out;

    cudaFuncSetAttribute(k_pre,   cudaFuncAttributeMaxDynamicSharedMemorySize, 163840);
    cudaFuncSetAttribute(k_edge3, cudaFuncAttributeMaxDynamicSharedMemorySize, 133120);
    cudaFuncSetAttribute(k_node1, cudaFuncAttributeMaxDynamicSharedMemorySize, 196608);
    cudaFuncSetAttribute(k_node2, cudaFuncAttributeMaxDynamicSharedMemorySize, 98304);

    k_zero<<<1024, 256>>>();
    k_deg<<<1024, 256>>>(ei);
    k_bsum<<<NBLK, 256>>>();
    k_sscan<<<1, 256>>>();
    k_wcur<<<NBLK, 256>>>();
    k_scatter<<<1024, 256>>>(ei);
    k_pre<<<152, 256, 163840>>>(h, We1);
    k_edge3<<<152, 512, 133120>>>(xz, We1, be1, We2, be2);
    k_node1<<<152, 256, 196608>>>(h, Wn1, bn1);
    k_node2<<<304, 256, 98304>>>(h, Wn2, bn2, out);
}

// round 9
// speedup vs baseline: 1.9480x; 1.1771x over previous
#include <cuda_runtime.h>
#include <cuda_bf16.h>
#include <math.h>
#include <stdint.h>

#define NN 50000
#define EE 800000
#define NTIL (EE / 128)         // 6250 tiles of 128 edges
#define NBLK ((NN + 255) / 256) // 196
#define NPT ((NN + 127) / 128)  // 391 node tiles of 128

typedef unsigned long long u64;
typedef unsigned int u32;

// Scratch (static __device__ — allocation-free per harness rules)
__device__ float g_AB[(size_t)NN * 256];   // A | B per node
__device__ float g_num[(size_t)NN * 128];  // segment sum accumulator
__device__ float g_t[(size_t)NN * 128];    // node hidden
__device__ int   g_deg[NN];
__device__ int   g_cur[NN];                // scatter cursors
__device__ int   g_bsum[256], g_bpre[256]; // scan partials
__device__ u64   g_edges[EE];              // sorted (col<<32 | row)

// silu via hardware tanh: x*sigmoid(x) = h + h*tanh(h), h = x/2
__device__ __forceinline__ float silu_t(float x) {
    float h = 0.5f * x, t;
    asm("tanh.approx.f32 %0, %1;" : "=f"(t) : "f"(h));
    return h + h * t;
}
__device__ __forceinline__ u32 bf2(float lo, float hi) {
    __nv_bfloat162 t = __float22bfloat162_rn(make_float2(lo, hi));
    return *(u32*)&t;
}
__device__ __forceinline__ u32 to_tf32(float x) {
    u32 t; asm("cvt.rna.tf32.f32 %0, %1;" : "=r"(t) : "f"(x)); return t;
}
__device__ __forceinline__ void mma16(float* d, u32 a0, u32 a1, u32 a2, u32 a3,
                                      u32 b0, u32 b1) {
    asm volatile("mma.sync.aligned.m16n8k16.row.col.f32.bf16.bf16.f32 "
        "{%0,%1,%2,%3}, {%4,%5,%6,%7}, {%8,%9}, {%0,%1,%2,%3};"
        : "+f"(d[0]), "+f"(d[1]), "+f"(d[2]), "+f"(d[3])
        : "r"(a0), "r"(a1), "r"(a2), "r"(a3), "r"(b0), "r"(b1));
}
__device__ __forceinline__ void mma8(float* d, u32 a0, u32 a1, u32 a2, u32 a3,
                                     u32 b0, u32 b1) {
    asm volatile("mma.sync.aligned.m16n8k8.row.col.f32.tf32.tf32.f32 "
        "{%0,%1,%2,%3}, {%4,%5,%6,%7}, {%8,%9}, {%0,%1,%2,%3};"
        : "+f"(d[0]), "+f"(d[1]), "+f"(d[2]), "+f"(d[3])
        : "r"(a0), "r"(a1), "r"(a2), "r"(a3), "r"(b0), "r"(b1));
}
__device__ __forceinline__ void red4(float* p, float a, float b, float c, float d) {
    asm volatile("red.global.add.v4.f32 [%0], {%1, %2, %3, %4};"
                 :: "l"(p), "f"(a), "f"(b), "f"(c), "f"(d) : "memory");
}

__global__ void k_zero() {
    int i = blockIdx.x * blockDim.x + threadIdx.x;
    int stride = gridDim.x * blockDim.x;
    float4 z = make_float4(0.f, 0.f, 0.f, 0.f);
    for (int j = i; j < NN * 128 / 4; j += stride) ((float4*)g_num)[j] = z;
    for (int j = i; j < NN; j += stride) g_deg[j] = 0;
}

__global__ void k_deg(const int* __restrict__ ei) {
    int i = blockIdx.x * blockDim.x + threadIdx.x;
    int stride = gridDim.x * blockDim.x;
    for (int e = i; e < EE; e += stride) atomicAdd(&g_deg[ei[e]], 1);
}

// -------- counting-sort scan (3 small kernels) + scatter --------
__global__ void k_bsum() {
    __shared__ int s[256];
    int b = blockIdx.x, tid = threadIdx.x, i = b * 256 + tid;
    s[tid] = (i < NN) ? g_deg[i] : 0;
    __syncthreads();
    for (int off = 128; off; off >>= 1) {
        if (tid < off) s[tid] += s[tid + off];
        __syncthreads();
    }
    if (!tid) g_bsum[b] = s[0];
}
__global__ void k_sscan() {
    __shared__ int s[256];
    int tid = threadIdx.x;
    int v0 = (tid < NBLK) ? g_bsum[tid] : 0;
    s[tid] = v0;
    __syncthreads();
    for (int off = 1; off < 256; off <<= 1) {
        int v = (tid >= off) ? s[tid - off] : 0;
        __syncthreads();
        s[tid] += v;
        __syncthreads();
    }
    if (tid < NBLK) g_bpre[tid] = s[tid] - v0;
}
__global__ void k_wcur() {
    __shared__ int s[256];
    int b = blockIdx.x, tid = threadIdx.x, i = b * 256 + tid;
    int d = (i < NN) ? g_deg[i] : 0;
    s[tid] = d;
    __syncthreads();
    for (int off = 1; off < 256; off <<= 1) {
        int v = (tid >= off) ? s[tid - off] : 0;
        __syncthreads();
        s[tid] += v;
        __syncthreads();
    }
    if (i < NN) g_cur[i] = s[tid] - d + g_bpre[b];
}
__global__ void k_scatter(const int* __restrict__ ei) {
    int i = blockIdx.x * blockDim.x + threadIdx.x;
    int stride = gridDim.x * blockDim.x;
    for (int e = i; e < EE; e += stride) {
        int r = ei[e], c = ei[EE + e];
        int pos = atomicAdd(&g_cur[r], 1);
        g_edges[pos] = ((u64)(u32)c << 32) | (u32)r;
    }
}

// ===================== tf32 MMA fabric (verified in R6 k_edge2) =====================
// As: [128 r][128 c] tf32, swizzle c' = c ^ ((r&7)<<2).
// B table: [128 k][128 n_phys] tf32, swizzle np ^ ((k&3)<<3), with column
// permutation nlog = ((nb>>1)<<4)+((c>>1)<<2)+((nb&1)<<1)+(c&1) so the epilogue
// thread (q,a8) owns logical col quad warp_n*32 + p*16 + q*4.

// Build one permuted+swizzled B table from row-major W (ldw = row stride, rows k0..k0+127)
__device__ __forceinline__ void build_btab(u32* Bs, const float* W, int k0, int ldw, int tid) {
    for (int idx = tid; idx < 16384; idx += 512) {
        int k = idx >> 7, np = idx & 127;
        int nb = np >> 3, c = np & 7;
        int nlog = ((nb >> 1) << 4) + ((c >> 1) << 2) + ((nb & 1) << 1) + (c & 1);
        Bs[k * 128 + (np ^ ((k & 3) << 3))] = to_tf32(W[(k0 + k) * ldw + nlog]);
    }
}

// MMA over K=128: acc[2][4][4] accumulates rows arow..arow+32, cols warp_n*32..+32
__device__ __forceinline__ void mma_pass(const u32* As, const u32* Bs,
                                         float acc[2][4][4], int arow, int warp_n,
                                         int q, int a8) {
    #pragma unroll
    for (int ks = 0; ks < 16; ks++) {
        int kk = ks * 8 + q;
        int swn = (kk & 3) << 3;
        u32 bf0[4], bf1[4];
        #pragma unroll
        for (int nb = 0; nb < 4; nb++) {
            int np = ((warp_n * 4 + nb) << 3) + a8;
            bf0[nb] = Bs[kk * 128 + (np ^ swn)];
            bf1[nb] = Bs[(kk + 4) * 128 + (np ^ ((kk + 4) & 3) * 8)];
        }
        #pragma unroll
        for (int mt = 0; mt < 2; mt++) {
            int rr = arow + mt * 16 + a8;
            int ca = kk ^ ((rr & 7) << 2);
            u32 a0 = As[rr * 128 + ca];
            u32 a2 = As[rr * 128 + (ca ^ 4)];
            u32 a1 = As[(rr + 8) * 128 + ca];
            u32 a3 = As[(rr + 8) * 128 + (ca ^ 4)];
            #pragma unroll
            for (int nb = 0; nb < 4; nb++)
                mma8(acc[mt][nb], a0, a1, a2, a3, bf0[nb], bf1[nb]);
        }
    }
}

// Producer: thread (r, kq) converts 32 floats of src row into As (tf32, swizzled)
__device__ __forceinline__ void fill_as(u32* As, const float4* src, int r, int kq,
                                        float scale) {
    int sw = (r & 7) << 2;
    #pragma unroll
    for (int i4 = 0; i4 < 8; i4++) {
        float4 v = src[i4];
        int c0 = kq * 32 + i4 * 4;
        uint4 o;
        o.x = to_tf32(v.x * scale); o.y = to_tf32(v.y * scale);
        o.z = to_tf32(v.z * scale); o.w = to_tf32(v.w * scale);
        *(uint4*)(As + r * 128 + (c0 ^ sw)) = o;
    }
}

// ---------------- K1: AB = h @ [We1_top | We1_bot] (tf32 MMA) -------------
__global__ void __launch_bounds__(512, 1) k_pre_mma(const float* __restrict__ h,
                                                    const float* __restrict__ We1) {
    extern __shared__ u32 smu[];
    u32* As  = smu;           // 16384 words
    u32* Bs0 = smu + 16384;
    u32* Bs1 = smu + 32768;
    int tid = threadIdx.x, wid = tid >> 5, lane = tid & 31;
    int warp_m = wid >> 2, warp_n = wid & 3;
    int q = lane & 3, a8 = lane >> 2;
    build_btab(Bs0, We1, 0, 128, tid);
    build_btab(Bs1, We1, 128, 128, tid);
    int r = tid >> 2, kq = tid & 3;
    int arow = warp_m * 32;
    for (int tile = blockIdx.x; tile < NPT; tile += gridDim.x) {
        __syncthreads();
        int node = min(tile * 128 + r, NN - 1);
        fill_as(As, (const float4*)(h + (size_t)node * 128 + kq * 32), r, kq, 1.0f);
        __syncthreads();
        #pragma unroll
        for (int half = 0; half < 2; half++) {
            float acc[2][4][4] = {};
            mma_pass(As, half ? Bs1 : Bs0, acc, arow, warp_n, q, a8);
            #pragma unroll
            for (int mt = 0; mt < 2; mt++) {
                int row0 = tile * 128 + arow + mt * 16 + a8;
                #pragma unroll
                for (int p = 0; p < 2; p++) {
                    int c = warp_n * 32 + p * 16 + q * 4;
                    int nA = 2 * p, nB = 2 * p + 1;
                    if (row0 < NN)
                        *(float4*)(g_AB + (size_t)row0 * 256 + half * 128 + c) =
                            make_float4(acc[mt][nA][0], acc[mt][nA][1],
                                        acc[mt][nB][0], acc[mt][nB][1]);
                    if (row0 + 8 < NN)
                        *(float4*)(g_AB + (size_t)(row0 + 8) * 256 + half * 128 + c) =
                            make_float4(acc[mt][nA][2], acc[mt][nA][3],
                                        acc[mt][nB][2], acc[mt][nB][3]);
                }
            }
        }
    }
}

// ---------------- K2: bf16 mma edge kernel, sorted edges, smem reduction (proven) ----
__global__ void __launch_bounds__(512, 1) k_edge3(
        const float* __restrict__ xz,
        const float* __restrict__ We1, const float* __restrict__ be1,
        const float* __restrict__ We2, const float* __restrict__ be2) {
    extern __shared__ u32 smu[];
    u32* Bs = smu;             // 8192 words
    u32* As = smu + 8192;      // 8192 words
    float* Cs = (float*)(smu + 16384);  // 128*132 floats
    __shared__ int s_row[128];
    __shared__ float sW1l[128], sB1[128];

    int tid = threadIdx.x, wid = tid >> 5, lane = tid & 31;
    int warp_m = wid >> 2, warp_n = wid & 3;
    int q = lane & 3, a8 = lane >> 2;

    for (int idx = tid; idx < 8192; idx += 512) {
        int n = idx >> 6, w = idx & 63;
        Bs[n * 64 + (w ^ ((n & 7) << 2))] =
            bf2(We2[(2 * w) * 128 + n], We2[(2 * w + 1) * 128 + n]);
    }
    if (tid < 128) { sW1l[tid] = We1[256 * 128 + tid]; sB1[tid] = be1[tid]; }

    int r = tid >> 2, kq = tid & 3;
    float4 be2v = *(const float4*)(be2 + lane * 4);

    for (int tile = blockIdx.x; tile < NTIL; tile += gridDim.x) {
        __syncthreads();
        {
            u64 pr = g_edges[(tile << 7) + r];
            int nr = (int)(u32)pr, nc = (int)(u32)(pr >> 32);
            if (kq == 0) s_row[r] = nr;
            float x0 = xz[nr * 3 + 0], y0 = xz[nr * 3 + 1], z0 = xz[nr * 3 + 2];
            float x1 = xz[nc * 3 + 0], y1 = xz[nc * 3 + 1], z1 = xz[nc * 3 + 2];
            float dx = x0 - x1, dy = y0 - y1, dz = z0 - z1;
            float u = (dx * dx + dy * dy + dz * dz) / (2.f * z0 * z1);
            float dist = acoshf(1.f + u);
            const float4* pa = (const float4*)(g_AB + (size_t)nr * 256 + kq * 32);
            const float4* pb = (const float4*)(g_AB + (size_t)nc * 256 + 128 + kq * 32);
            int sw = (r & 7) << 2;
            #pragma unroll
            for (int j = 0; j < 4; j++) {
                uint4 o;
                {
                    float4 a = pa[2 * j], b = pb[2 * j];
                    int c0 = kq * 32 + 8 * j;
                    float4 w  = *(const float4*)(sW1l + c0);
                    float4 bb = *(const float4*)(sB1 + c0);
                    float v0 = silu_t(a.x + b.x + dist * w.x + bb.x);
                    float v1 = silu_t(a.y + b.y + dist * w.y + bb.y);
                    float v2 = silu_t(a.z + b.z + dist * w.z + bb.z);
                    float v3 = silu_t(a.w + b.w + dist * w.w + bb.w);
                    o.x = bf2(v0, v1); o.y = bf2(v2, v3);
                }
                {
                    float4 a = pa[2 * j + 1], b = pb[2 * j + 1];
                    int c0 = kq * 32 + 8 * j + 4;
                    float4 w  = *(const float4*)(sW1l + c0);
                    float4 bb = *(const float4*)(sB1 + c0);
                    float v0 = silu_t(a.x + b.x + dist * w.x + bb.x);
                    float v1 = silu_t(a.y + b.y + dist * w.y + bb.y);
                    float v2 = silu_t(a.z + b.z + dist * w.z + bb.z);
                    float v3 = silu_t(a.w + b.w + dist * w.w + bb.w);
                    o.z = bf2(v0, v1); o.w = bf2(v2, v3);
                }
                int w0 = kq * 16 + 4 * j;
                *(uint4*)(As + r * 64 + (w0 ^ sw)) = o;
            }
        }
        __syncthreads();

        float acc[2][4][4];
        #pragma unroll
        for (int mt = 0; mt < 2; mt++)
            #pragma unroll
            for (int nb = 0; nb < 4; nb++)
                #pragma unroll
                for (int x = 0; x < 4; x++) acc[mt][nb][x] = 0.f;

        int arow = warp_m * 32;
        #pragma unroll
        for (int ks = 0; ks < 8; ks++) {
            u32 bf0[4], bf1[4];
            #pragma unroll
            for (int nb = 0; nb < 4; nb++) {
                int n = warp_n * 32 + nb * 8 + a8;
                int sw = (n & 7) << 2;
                bf0[nb] = Bs[n * 64 + ((ks * 8 + q) ^ sw)];
                bf1[nb] = Bs[n * 64 + ((ks * 8 + q + 4) ^ sw)];
            }
            #pragma unroll
            for (int mt = 0; mt < 2; mt++) {
                int r0 = arow + mt * 16 + a8;
                int sw = (r0 & 7) << 2;
                u32 a0 = As[r0 * 64 + ((ks * 8 + q) ^ sw)];
                u32 a1 = As[(r0 + 8) * 64 + ((ks * 8 + q) ^ sw)];
                u32 a2 = As[r0 * 64 + ((ks * 8 + q + 4) ^ sw)];
                u32 a3 = As[(r0 + 8) * 64 + ((ks * 8 + q + 4) ^ sw)];
                #pragma unroll
                for (int nb = 0; nb < 4; nb++)
                    mma16(acc[mt][nb], a0, a1, a2, a3, bf0[nb], bf1[nb]);
            }
        }

        #pragma unroll
        for (int mt = 0; mt < 2; mt++) {
            int r0 = arow + mt * 16 + a8;
            #pragma unroll
            for (int nb = 0; nb < 4; nb++) {
                int c = warp_n * 32 + nb * 8 + 2 * q;
                *(float2*)(Cs + r0 * 132 + c) = make_float2(acc[mt][nb][0], acc[mt][nb][1]);
                *(float2*)(Cs + (r0 + 8) * 132 + c) = make_float2(acc[mt][nb][2], acc[mt][nb][3]);
            }
        }
        __syncthreads();

        {
            int rb = wid * 8;
            int cur = s_row[rb];
            float4 sum;
            {
                float4 c = *(const float4*)(Cs + rb * 132 + lane * 4);
                sum.x = silu_t(c.x + be2v.x); sum.y = silu_t(c.y + be2v.y);
                sum.z = silu_t(c.z + be2v.z); sum.w = silu_t(c.w + be2v.w);
            }
            #pragma unroll
            for (int i = 1; i < 8; i++) {
                int rr = rb + i;
                int dest = s_row[rr];
                float4 c = *(const float4*)(Cs + rr * 132 + lane * 4);
                float4 v;
                v.x = silu_t(c.x + be2v.x); v.y = silu_t(c.y + be2v.y);
                v.z = silu_t(c.z + be2v.z); v.w = silu_t(c.w + be2v.w);
                if (dest != cur) {
                    red4(g_num + (size_t)cur * 128 + lane * 4, sum.x, sum.y, sum.z, sum.w);
                    sum = v; cur = dest;
                } else {
                    sum.x += v.x; sum.y += v.y; sum.z += v.z; sum.w += v.w;
                }
            }
            red4(g_num + (size_t)cur * 128 + lane * 4, sum.x, sum.y, sum.z, sum.w);
        }
    }
}

// ---------------- K3a: t = silu([h, agg] @ Wn1 + bn1) (tf32 MMA, split-K) ---------
__global__ void __launch_bounds__(512, 1) k_node1_mma(const float* __restrict__ h,
        const float* __restrict__ Wn1, const float* __restrict__ bn1) {
    extern __shared__ u32 smu[];
    u32* As  = smu;
    u32* Bs0 = smu + 16384;
    u32* Bs1 = smu + 32768;
    int tid = threadIdx.x, wid = tid >> 5, lane = tid & 31;
    int warp_m = wid >> 2, warp_n = wid & 3;
    int q = lane & 3, a8 = lane >> 2;
    build_btab(Bs0, Wn1, 0, 128, tid);
    build_btab(Bs1, Wn1, 128, 128, tid);
    int r = tid >> 2, kq = tid & 3;
    int arow = warp_m * 32;
    float4 bv[2];
    bv[0] = *(const float4*)(bn1 + warp_n * 32 + q * 4);
    bv[1] = *(const float4*)(bn1 + warp_n * 32 + 16 + q * 4);
    for (int tile = blockIdx.x; tile < NPT; tile += gridDim.x) {
        __syncthreads();
        int node = min(tile * 128 + r, NN - 1);
        fill_as(As, (const float4*)(h + (size_t)node * 128 + kq * 32), r, kq, 1.0f);
        __syncthreads();
        float acc[2][4][4] = {};
        mma_pass(As, Bs0, acc, arow, warp_n, q, a8);
        __syncthreads();
        float scale = 1.0f / fmaxf((float)g_deg[node], 1.0f);
        fill_as(As, (const float4*)(g_num + (size_t)node * 128 + kq * 32), r, kq, scale);
        __syncthreads();
        mma_pass(As, Bs1, acc, arow, warp_n, q, a8);
        #pragma unroll
        for (int mt = 0; mt < 2; mt++) {
            int row0 = tile * 128 + arow + mt * 16 + a8;
            #pragma unroll
            for (int p = 0; p < 2; p++) {
                int c = warp_n * 32 + p * 16 + q * 4;
                int nA = 2 * p, nB = 2 * p + 1;
                if (row0 < NN)
                    *(float4*)(g_t + (size_t)row0 * 128 + c) =
                        make_float4(silu_t(acc[mt][nA][0] + bv[p].x),
                                    silu_t(acc[mt][nA][1] + bv[p].y),
                                    silu_t(acc[mt][nB][0] + bv[p].z),
                                    silu_t(acc[mt][nB][1] + bv[p].w));
                if (row0 + 8 < NN)
                    *(float4*)(g_t + (size_t)(row0 + 8) * 128 + c) =
                        make_float4(silu_t(acc[mt][nA][2] + bv[p].x),
                                    silu_t(acc[mt][nA][3] + bv[p].y),
                                    silu_t(acc[mt][nB][2] + bv[p].z),
                                    silu_t(acc[mt][nB][3] + bv[p].w));
            }
        }
    }
}

// ---------------- K3b: out = h + t @ Wn2 + bn2 (tf32 MMA) -----------------
__global__ void __launch_bounds__(512, 1) k_node2_mma(const float* __restrict__ h,
        const float* __restrict__ Wn2, const float* __restrict__ bn2,
        float* __restrict__ out) {
    extern __shared__ u32 smu[];
    u32* As = smu;
    u32* Bs = smu + 16384;
    int tid = threadIdx.x, wid = tid >> 5, lane = tid & 31;
    int warp_m = wid >> 2, warp_n = wid & 3;
    int q = lane & 3, a8 = lane >> 2;
    build_btab(Bs, Wn2, 0, 128, tid);
    int r = tid >> 2, kq = tid & 3;
    int arow = warp_m * 32;
    float4 bv[2];
    bv[0] = *(const float4*)(bn2 + warp_n * 32 + q * 4);
    bv[1] = *(const float4*)(bn2 + warp_n * 32 + 16 + q * 4);
    for (int tile = blockIdx.x; tile < NPT; tile += gridDim.x) {
        __syncthreads();
        int node = min(tile * 128 + r, NN - 1);
        fill_as(As, (const float4*)(g_t + (size_t)node * 128 + kq * 32), r, kq, 1.0f);
        __syncthreads();
        float acc[2][4][4] = {};
        mma_pass(As, Bs, acc, arow, warp_n, q, a8);
        #pragma unroll
        for (int mt = 0; mt < 2; mt++) {
            int row0 = tile * 128 + arow + mt * 16 + a8;
            #pragma unroll
            for (int p = 0; p < 2; p++) {
                int c = warp_n * 32 + p * 16 + q * 4;
                int nA = 2 * p, nB = 2 * p + 1;
                if (row0 < NN) {
                    float4 hv = *(const float4*)(h + (size_t)row0 * 128 + c);
                    *(float4*)(out + (size_t)row0 * 128 + c) =
                        make_float4(hv.x + acc[mt][nA][0] + bv[p].x,
                                    hv.y + acc[mt][nA][1] + bv[p].y,
                                    hv.z + acc[mt][nB][0] + bv[p].z,
                                    hv.w + acc[mt][nB][1] + bv[p].w);
                }
                if (row0 + 8 < NN) {
                    float4 hv = *(const float4*)(h + (size_t)(row0 + 8) * 128 + c);
                    *(float4*)(out + (size_t)(row0 + 8) * 128 + c) =
                        make_float4(hv.x + acc[mt][nA][2] + bv[p].x,
                                    hv.y + acc[mt][nA][3] + bv[p].y,
                                    hv.z + acc[mt][nB][2] + bv[p].z,
                                    hv.w + acc[mt][nB][3] + bv[p].w);
                }
            }
        }
    }
}

extern "C" void kernel_launch(void* const* d_in, const int* in_sizes, int n_in,
                              void* d_out, int out_size) {
    (void)in_sizes; (void)n_in; (void)out_size;
    const float* xz  = (const float*)d_in[0];
    const float* h   = (const float*)d_in[1];
    const float* We1 = (const float*)d_in[2];
    const float* be1 = (const float*)d_in[3];
    const float* We2 = (const float*)d_in[4];
    const float* be2 = (const float*)d_in[5];
    const float* Wn1 = (const float*)d_in[6];
    const float* bn1 = (const float*)d_in[7];
    const float* Wn2 = (const float*)d_in[8];
    const float* bn2 = (const float*)d_in[9];
    const int*   ei  = (const int*)d_in[10];
    float* out = (float*)d_out;

    cudaFuncSetAttribute(k_pre_mma,   cudaFuncAttributeMaxDynamicSharedMemorySize, 196608);
    cudaFuncSetAttribute(k_edge3,     cudaFuncAttributeMaxDynamicSharedMemorySize, 133120);
    cudaFuncSetAttribute(k_node1_mma, cudaFuncAttributeMaxDynamicSharedMemorySize, 196608);
    cudaFuncSetAttribute(k_node2_mma, cudaFuncAttributeMaxDynamicSharedMemorySize, 131072);

    k_zero<<<1024, 256>>>();
    k_deg<<<1024, 256>>>(ei);
    k_bsum<<<NBLK, 256>>>();
    k_sscan<<<1, 256>>>();
    k_wcur<<<NBLK, 256>>>();
    k_scatter<<<1024, 256>>>(ei);
    k_pre_mma<<<152, 512, 196608>>>(h, We1);
    k_edge3<<<152, 512, 133120>>>(xz, We1, be1, We2, be2);
    k_node1_mma<<<152, 512, 196608>>>(h, Wn1, bn1);
    k_node2_mma<<<152, 512, 131072>>>(h, Wn2, bn2, out);
}

// round 10
// speedup vs baseline: 2.5101x; 1.2885x over previous
#include <cuda_runtime.h>
#include <cuda_bf16.h>
#include <math.h>
#include <stdint.h>

#define NN 50000
#define EE 800000
#define NTIL2 (EE / 64)         // 12500 tiles of 64 edges
#define NBLK ((NN + 255) / 256) // 196
#define NPT ((NN + 127) / 128)  // 391 node tiles of 128

typedef unsigned long long u64;
typedef unsigned int u32;

// Scratch (static __device__ — allocation-free per harness rules)
__device__ u32   g_ABh[(size_t)NN * 128];  // A | B per node, bf16x2 packed (64+64 words)
__device__ float g_num[(size_t)NN * 128];  // segment sum accumulator
__device__ float g_t[(size_t)NN * 128];    // node hidden
__device__ int   g_deg[NN];
__device__ int   g_cur[NN];                // scatter cursors
__device__ int   g_bsum[256], g_bpre[256]; // scan partials
__device__ u64   g_edges[EE];              // sorted (col<<32 | row)

// silu via hardware tanh: x*sigmoid(x) = h + h*tanh(h), h = x/2
__device__ __forceinline__ float silu_t(float x) {
    float h = 0.5f * x, t;
    asm("tanh.approx.f32 %0, %1;" : "=f"(t) : "f"(h));
    return h + h * t;
}
__device__ __forceinline__ u32 bf2(float lo, float hi) {
    __nv_bfloat162 t = __float22bfloat162_rn(make_float2(lo, hi));
    return *(u32*)&t;
}
__device__ __forceinline__ float2 ubf2(u32 v) {
    return __bfloat1622float2(*(__nv_bfloat162*)&v);
}
__device__ __forceinline__ u32 to_tf32(float x) {
    u32 t; asm("cvt.rna.tf32.f32 %0, %1;" : "=r"(t) : "f"(x)); return t;
}
__device__ __forceinline__ void mma16(float* d, u32 a0, u32 a1, u32 a2, u32 a3,
                                      u32 b0, u32 b1) {
    asm volatile("mma.sync.aligned.m16n8k16.row.col.f32.bf16.bf16.f32 "
        "{%0,%1,%2,%3}, {%4,%5,%6,%7}, {%8,%9}, {%0,%1,%2,%3};"
        : "+f"(d[0]), "+f"(d[1]), "+f"(d[2]), "+f"(d[3])
        : "r"(a0), "r"(a1), "r"(a2), "r"(a3), "r"(b0), "r"(b1));
}
__device__ __forceinline__ void mma8(float* d, u32 a0, u32 a1, u32 a2, u32 a3,
                                     u32 b0, u32 b1) {
    asm volatile("mma.sync.aligned.m16n8k8.row.col.f32.tf32.tf32.f32 "
        "{%0,%1,%2,%3}, {%4,%5,%6,%7}, {%8,%9}, {%0,%1,%2,%3};"
        : "+f"(d[0]), "+f"(d[1]), "+f"(d[2]), "+f"(d[3])
        : "r"(a0), "r"(a1), "r"(a2), "r"(a3), "r"(b0), "r"(b1));
}
__device__ __forceinline__ void red4(float* p, float a, float b, float c, float d) {
    asm volatile("red.global.add.v4.f32 [%0], {%1, %2, %3, %4};"
                 :: "l"(p), "f"(a), "f"(b), "f"(c), "f"(d) : "memory");
}

__global__ void k_zero() {
    int i = blockIdx.x * blockDim.x + threadIdx.x;
    int stride = gridDim.x * blockDim.x;
    float4 z = make_float4(0.f, 0.f, 0.f, 0.f);
    for (int j = i; j < NN * 128 / 4; j += stride) ((float4*)g_num)[j] = z;
    for (int j = i; j < NN; j += stride) g_deg[j] = 0;
}

__global__ void k_deg(const int* __restrict__ ei) {
    int i = blockIdx.x * blockDim.x + threadIdx.x;
    int stride = gridDim.x * blockDim.x;
    for (int e = i; e < EE; e += stride) atomicAdd(&g_deg[ei[e]], 1);
}

// -------- counting-sort scan (3 small kernels) + scatter --------
__global__ void k_bsum() {
    __shared__ int s[256];
    int b = blockIdx.x, tid = threadIdx.x, i = b * 256 + tid;
    s[tid] = (i < NN) ? g_deg[i] : 0;
    __syncthreads();
    for (int off = 128; off; off >>= 1) {
        if (tid < off) s[tid] += s[tid + off];
        __syncthreads();
    }
    if (!tid) g_bsum[b] = s[0];
}
__global__ void k_sscan() {
    __shared__ int s[256];
    int tid = threadIdx.x;
    int v0 = (tid < NBLK) ? g_bsum[tid] : 0;
    s[tid] = v0;
    __syncthreads();
    for (int off = 1; off < 256; off <<= 1) {
        int v = (tid >= off) ? s[tid - off] : 0;
        __syncthreads();
        s[tid] += v;
        __syncthreads();
    }
    if (tid < NBLK) g_bpre[tid] = s[tid] - v0;
}
__global__ void k_wcur() {
    __shared__ int s[256];
    int b = blockIdx.x, tid = threadIdx.x, i = b * 256 + tid;
    int d = (i < NN) ? g_deg[i] : 0;
    s[tid] = d;
    __syncthreads();
    for (int off = 1; off < 256; off <<= 1) {
        int v = (tid >= off) ? s[tid - off] : 0;
        __syncthreads();
        s[tid] += v;
        __syncthreads();
    }
    if (i < NN) g_cur[i] = s[tid] - d + g_bpre[b];
}
__global__ void k_scatter(const int* __restrict__ ei) {
    int i = blockIdx.x * blockDim.x + threadIdx.x;
    int stride = gridDim.x * blockDim.x;
    for (int e = i; e < EE; e += stride) {
        int r = ei[e], c = ei[EE + e];
        int pos = atomicAdd(&g_cur[r], 1);
        g_edges[pos] = ((u64)(u32)c << 32) | (u32)r;
    }
}

// ===================== tf32 MMA fabric (verified R6/R9) =====================
// As: [128 r][128 c] tf32, swizzle c' = c ^ ((r&7)<<2).
// B table: [128 k][128 n_phys] tf32, swizzle np ^ ((k&3)<<3), column permutation
// nlog = ((nb>>1)<<4)+((c>>1)<<2)+((nb&1)<<1)+(c&1).

__device__ __forceinline__ void build_btab(u32* Bs, const float* W, int k0, int ldw, int tid) {
    for (int idx = tid; idx < 16384; idx += 512) {
        int k = idx >> 7, np = idx & 127;
        int nb = np >> 3, c = np & 7;
        int nlog = ((nb >> 1) << 4) + ((c >> 1) << 2) + ((nb & 1) << 1) + (c & 1);
        Bs[k * 128 + (np ^ ((k & 3) << 3))] = to_tf32(W[(k0 + k) * ldw + nlog]);
    }
}

__device__ __forceinline__ void mma_pass(const u32* As, const u32* Bs,
                                         float acc[2][4][4], int arow, int warp_n,
                                         int q, int a8) {
    #pragma unroll
    for (int ks = 0; ks < 16; ks++) {
        int kk = ks * 8 + q;
        int swn = (kk & 3) << 3;
        u32 bf0[4], bf1[4];
        #pragma unroll
        for (int nb = 0; nb < 4; nb++) {
            int np = ((warp_n * 4 + nb) << 3) + a8;
            bf0[nb] = Bs[kk * 128 + (np ^ swn)];
            bf1[nb] = Bs[(kk + 4) * 128 + (np ^ ((kk + 4) & 3) * 8)];
        }
        #pragma unroll
        for (int mt = 0; mt < 2; mt++) {
            int rr = arow + mt * 16 + a8;
            int ca = kk ^ ((rr & 7) << 2);
            u32 a0 = As[rr * 128 + ca];
            u32 a2 = As[rr * 128 + (ca ^ 4)];
            u32 a1 = As[(rr + 8) * 128 + ca];
            u32 a3 = As[(rr + 8) * 128 + (ca ^ 4)];
            #pragma unroll
            for (int nb = 0; nb < 4; nb++)
                mma8(acc[mt][nb], a0, a1, a2, a3, bf0[nb], bf1[nb]);
        }
    }
}

__device__ __forceinline__ void fill_as(u32* As, const float4* src, int r, int kq,
                                        float scale) {
    int sw = (r & 7) << 2;
    #pragma unroll
    for (int i4 = 0; i4 < 8; i4++) {
        float4 v = src[i4];
        int c0 = kq * 32 + i4 * 4;
        uint4 o;
        o.x = to_tf32(v.x * scale); o.y = to_tf32(v.y * scale);
        o.z = to_tf32(v.z * scale); o.w = to_tf32(v.w * scale);
        *(uint4*)(As + r * 128 + (c0 ^ sw)) = o;
    }
}

// ---------------- K1: g_ABh = bf16(h @ [We1_top | We1_bot]) (tf32 MMA) -------------
__global__ void __launch_bounds__(512, 1) k_pre_mma(const float* __restrict__ h,
                                                    const float* __restrict__ We1) {
    extern __shared__ u32 smu[];
    u32* As  = smu;           // 16384 words
    u32* Bs0 = smu + 16384;
    u32* Bs1 = smu + 32768;
    int tid = threadIdx.x, wid = tid >> 5, lane = tid & 31;
    int warp_m = wid >> 2, warp_n = wid & 3;
    int q = lane & 3, a8 = lane >> 2;
    build_btab(Bs0, We1, 0, 128, tid);
    build_btab(Bs1, We1, 128, 128, tid);
    int r = tid >> 2, kq = tid & 3;
    int arow = warp_m * 32;
    for (int tile = blockIdx.x; tile < NPT; tile += gridDim.x) {
        __syncthreads();
        int node = min(tile * 128 + r, NN - 1);
        fill_as(As, (const float4*)(h + (size_t)node * 128 + kq * 32), r, kq, 1.0f);
        __syncthreads();
        #pragma unroll
        for (int half = 0; half < 2; half++) {
            float acc[2][4][4] = {};
            mma_pass(As, half ? Bs1 : Bs0, acc, arow, warp_n, q, a8);
            #pragma unroll
            for (int mt = 0; mt < 2; mt++) {
                int row0 = tile * 128 + arow + mt * 16 + a8;
                #pragma unroll
                for (int p = 0; p < 2; p++) {
                    int c = warp_n * 32 + p * 16 + q * 4;
                    int nA = 2 * p, nB = 2 * p + 1;
                    if (row0 < NN) {
                        uint2 o = make_uint2(bf2(acc[mt][nA][0], acc[mt][nA][1]),
                                             bf2(acc[mt][nB][0], acc[mt][nB][1]));
                        *(uint2*)(g_ABh + (size_t)row0 * 128 + half * 64 + (c >> 1)) = o;
                    }
                    if (row0 + 8 < NN) {
                        uint2 o = make_uint2(bf2(acc[mt][nA][2], acc[mt][nA][3]),
                                             bf2(acc[mt][nB][2], acc[mt][nB][3]));
                        *(uint2*)(g_ABh + (size_t)(row0 + 8) * 128 + half * 64 + (c >> 1)) = o;
                    }
                }
            }
        }
    }
}

// ---------------- K2: bf16 mma edge kernel, M=64 tiles, 2 CTAs/SM ----------------
// smem: Bs [128n][64 kpairs] bf16 (32KB), As [64r][64 kpairs] bf16 (16KB),
//       Cs [64][132] f32 (33KB). 256 thr, 8 warps as 2(M)x4(N).
__global__ void __launch_bounds__(256, 2) k_edge4(
        const float* __restrict__ xz,
        const float* __restrict__ We1, const float* __restrict__ be1,
        const float* __restrict__ We2, const float* __restrict__ be2) {
    extern __shared__ u32 smu[];
    u32* Bs = smu;                       // 8192 words
    u32* As = smu + 8192;                // 4096 words
    float* Cs = (float*)(smu + 12288);   // 64*132 floats
    __shared__ int s_row[64];
    __shared__ float sW1l[128], sB1[128];

    int tid = threadIdx.x, wid = tid >> 5, lane = tid & 31;
    int warp_m = wid >> 2, warp_n = wid & 3;   // warp_m 0..1, warp_n 0..3
    int q = lane & 3, a8 = lane >> 2;

    // bf16 B table: Bs[n][w] = (We2[2w][n], We2[2w+1][n]), swizzled
    for (int idx = tid; idx < 8192; idx += 256) {
        int n = idx >> 6, w = idx & 63;
        Bs[n * 64 + (w ^ ((n & 7) << 2))] =
            bf2(We2[(2 * w) * 128 + n], We2[(2 * w + 1) * 128 + n]);
    }
    if (tid < 128) { sW1l[tid] = We1[256 * 128 + tid]; sB1[tid] = be1[tid]; }

    int r = tid >> 2, kq = tid & 3;      // r 0..63, kq 0..3
    float4 be2v = *(const float4*)(be2 + lane * 4);

    for (int tile = blockIdx.x; tile < NTIL2; tile += gridDim.x) {
        __syncthreads();
        // ---- producer: pre = silu(A[row]+B[col]+dist*w1l+b1) -> bf16 As ----
        {
            u64 pr = g_edges[(tile << 6) + r];
            int nr = (int)(u32)pr, nc = (int)(u32)(pr >> 32);
            if (kq == 0) s_row[r] = nr;
            float x0 = xz[nr * 3 + 0], y0 = xz[nr * 3 + 1], z0 = xz[nr * 3 + 2];
            float x1 = xz[nc * 3 + 0], y1 = xz[nc * 3 + 1], z1 = xz[nc * 3 + 2];
            float dx = x0 - x1, dy = y0 - y1, dz = z0 - z1;
            float u = (dx * dx + dy * dy + dz * dz) / (2.f * z0 * z1);
            float dist = acoshf(1.f + u);
            const uint4* pa = (const uint4*)(g_ABh + (size_t)nr * 128 + kq * 16);
            const uint4* pb = (const uint4*)(g_ABh + (size_t)nc * 128 + 64 + kq * 16);
            int sw = (r & 7) << 2;
            #pragma unroll
            for (int j = 0; j < 4; j++) {        // uint4 = 8 bf16 feats
                uint4 a4 = pa[j], b4 = pb[j];
                int c0 = kq * 32 + 8 * j;
                float2 a0 = ubf2(a4.x), a1 = ubf2(a4.y), a2 = ubf2(a4.z), a3 = ubf2(a4.w);
                float2 b0 = ubf2(b4.x), b1 = ubf2(b4.y), b2 = ubf2(b4.z), b3 = ubf2(b4.w);
                float4 w0 = *(const float4*)(sW1l + c0);
                float4 w1 = *(const float4*)(sW1l + c0 + 4);
                float4 e0 = *(const float4*)(sB1 + c0);
                float4 e1 = *(const float4*)(sB1 + c0 + 4);
                uint4 o;
                o.x = bf2(silu_t(a0.x + b0.x + dist * w0.x + e0.x),
                          silu_t(a0.y + b0.y + dist * w0.y + e0.y));
                o.y = bf2(silu_t(a1.x + b1.x + dist * w0.z + e0.z),
                          silu_t(a1.y + b1.y + dist * w0.w + e0.w));
                o.z = bf2(silu_t(a2.x + b2.x + dist * w1.x + e1.x),
                          silu_t(a2.y + b2.y + dist * w1.y + e1.y));
                o.w = bf2(silu_t(a3.x + b3.x + dist * w1.z + e1.z),
                          silu_t(a3.y + b3.y + dist * w1.w + e1.w));
                int wd = kq * 16 + 4 * j;
                *(uint4*)(As + r * 64 + (wd ^ sw)) = o;
            }
        }
        __syncthreads();

        // ---- MMA: warp (warp_m, warp_n) -> rows warp_m*32+, cols warp_n*32+ ----
        float acc[2][4][4];
        #pragma unroll
        for (int mt = 0; mt < 2; mt++)
            #pragma unroll
            for (int nb = 0; nb < 4; nb++)
                #pragma unroll
                for (int x = 0; x < 4; x++) acc[mt][nb][x] = 0.f;

        int arow = warp_m * 32;
        #pragma unroll
        for (int ks = 0; ks < 8; ks++) {
            u32 bf0[4], bf1[4];
            #pragma unroll
            for (int nb = 0; nb < 4; nb++) {
                int n = warp_n * 32 + nb * 8 + a8;
                int sw = (n & 7) << 2;
                bf0[nb] = Bs[n * 64 + ((ks * 8 + q) ^ sw)];
                bf1[nb] = Bs[n * 64 + ((ks * 8 + q + 4) ^ sw)];
            }
            #pragma unroll
            for (int mt = 0; mt < 2; mt++) {
                int r0 = arow + mt * 16 + a8;
                int sw = (r0 & 7) << 2;
                u32 a0 = As[r0 * 64 + ((ks * 8 + q) ^ sw)];
                u32 a1 = As[(r0 + 8) * 64 + ((ks * 8 + q) ^ sw)];
                u32 a2 = As[r0 * 64 + ((ks * 8 + q + 4) ^ sw)];
                u32 a3 = As[(r0 + 8) * 64 + ((ks * 8 + q + 4) ^ sw)];
                #pragma unroll
                for (int nb = 0; nb < 4; nb++)
                    mma16(acc[mt][nb], a0, a1, a2, a3, bf0[nb], bf1[nb]);
            }
        }

        // ---- stage C fragments to Cs (stride 132) ----
        #pragma unroll
        for (int mt = 0; mt < 2; mt++) {
            int r0 = arow + mt * 16 + a8;
            #pragma unroll
            for (int nb = 0; nb < 4; nb++) {
                int c = warp_n * 32 + nb * 8 + 2 * q;
                *(float2*)(Cs + r0 * 132 + c) = make_float2(acc[mt][nb][0], acc[mt][nb][1]);
                *(float2*)(Cs + (r0 + 8) * 132 + c) = make_float2(acc[mt][nb][2], acc[mt][nb][3]);
            }
        }
        __syncthreads();

        // ---- segmented reduction: warp = rows [wid*8, +8), lane = col quad ----
        {
            int rb = wid * 8;
            int cur = s_row[rb];
            float4 sum;
            {
                float4 c = *(const float4*)(Cs + rb * 132 + lane * 4);
                sum.x = silu_t(c.x + be2v.x); sum.y = silu_t(c.y + be2v.y);
                sum.z = silu_t(c.z + be2v.z); sum.w = silu_t(c.w + be2v.w);
            }
            #pragma unroll
            for (int i = 1; i < 8; i++) {
                int rr = rb + i;
                int dest = s_row[rr];
                float4 c = *(const float4*)(Cs + rr * 132 + lane * 4);
                float4 v;
                v.x = silu_t(c.x + be2v.x); v.y = silu_t(c.y + be2v.y);
                v.z = silu_t(c.z + be2v.z); v.w = silu_t(c.w + be2v.w);
                if (dest != cur) {
                    red4(g_num + (size_t)cur * 128 + lane * 4, sum.x, sum.y, sum.z, sum.w);
                    sum = v; cur = dest;
                } else {
                    sum.x += v.x; sum.y += v.y; sum.z += v.z; sum.w += v.w;
                }
            }
            red4(g_num + (size_t)cur * 128 + lane * 4, sum.x, sum.y, sum.z, sum.w);
        }
    }
}

// ---------------- K3a: t = silu([h, agg] @ Wn1 + bn1) (tf32 MMA, split-K) ---------
__global__ void __launch_bounds__(512, 1) k_node1_mma(const float* __restrict__ h,
        const float* __restrict__ Wn1, const float* __restrict__ bn1) {
    extern __shared__ u32 smu[];
    u32* As  = smu;
    u32* Bs0 = smu + 16384;
    u32* Bs1 = smu + 32768;
    int tid = threadIdx.x, wid = tid >> 5, lane = tid & 31;
    int warp_m = wid >> 2, warp_n = wid & 3;
    int q = lane & 3, a8 = lane >> 2;
    build_btab(Bs0, Wn1, 0, 128, tid);
    build_btab(Bs1, Wn1, 128, 128, tid);
    int r = tid >> 2, kq = tid & 3;
    int arow = warp_m * 32;
    float4 bv[2];
    bv[0] = *(const float4*)(bn1 + warp_n * 32 + q * 4);
    bv[1] = *(const float4*)(bn1 + warp_n * 32 + 16 + q * 4);
    for (int tile = blockIdx.x; tile < NPT; tile += gridDim.x) {
        __syncthreads();
        int node = min(tile * 128 + r, NN - 1);
        fill_as(As, (const float4*)(h + (size_t)node * 128 + kq * 32), r, kq, 1.0f);
        __syncthreads();
        float acc[2][4][4] = {};
        mma_pass(As, Bs0, acc, arow, warp_n, q, a8);
        __syncthreads();
        float scale = 1.0f / fmaxf((float)g_deg[node], 1.0f);
        fill_as(As, (const float4*)(g_num + (size_t)node * 128 + kq * 32), r, kq, scale);
        __syncthreads();
        mma_pass(As, Bs1, acc, arow, warp_n, q, a8);
        #pragma unroll
        for (int mt = 0; mt < 2; mt++) {
            int row0 = tile * 128 + arow + mt * 16 + a8;
            #pragma unroll
            for (int p = 0; p < 2; p++) {
                int c = warp_n * 32 + p * 16 + q * 4;
                int nA = 2 * p, nB = 2 * p + 1;
                if (row0 < NN)
                    *(float4*)(g_t + (size_t)row0 * 128 + c) =
                        make_float4(silu_t(acc[mt][nA][0] + bv[p].x),
                                    silu_t(acc[mt][nA][1] + bv[p].y),
                                    silu_t(acc[mt][nB][0] + bv[p].z),
                                    silu_t(acc[mt][nB][1] + bv[p].w));
                if (row0 + 8 < NN)
                    *(float4*)(g_t + (size_t)(row0 + 8) * 128 + c) =
                        make_float4(silu_t(acc[mt][nA][2] + bv[p].x),
                                    silu_t(acc[mt][nA][3] + bv[p].y),
                                    silu_t(acc[mt][nB][2] + bv[p].z),
                                    silu_t(acc[mt][nB][3] + bv[p].w));
            }
        }
    }
}

// ---------------- K3b: out = h + t @ Wn2 + bn2 (tf32 MMA) -----------------
__global__ void __launch_bounds__(512, 1) k_node2_mma(const float* __restrict__ h,
        const float* __restrict__ Wn2, const float* __restrict__ bn2,
        float* __restrict__ out) {
    extern __shared__ u32 smu[];
    u32* As = smu;
    u32* Bs = smu + 16384;
    int tid = threadIdx.x, wid = tid >> 5, lane = tid & 31;
    int warp_m = wid >> 2, warp_n = wid & 3;
    int q = lane & 3, a8 = lane >> 2;
    build_btab(Bs, Wn2, 0, 128, tid);
    int r = tid >> 2, kq = tid & 3;
    int arow = warp_m * 32;
    float4 bv[2];
    bv[0] = *(const float4*)(bn2 + warp_n * 32 + q * 4);
    bv[1] = *(const float4*)(bn2 + warp_n * 32 + 16 + q * 4);
    for (int tile = blockIdx.x; tile < NPT; tile += gridDim.x) {
        __syncthreads();
        int node = min(tile * 128 + r, NN - 1);
        fill_as(As, (const float4*)(g_t + (size_t)node * 128 + kq * 32), r, kq, 1.0f);
        __syncthreads();
        float acc[2][4][4] = {};
        mma_pass(As, Bs, acc, arow, warp_n, q, a8);
        #pragma unroll
        for (int mt = 0; mt < 2; mt++) {
            int row0 = tile * 128 + arow + mt * 16 + a8;
            #pragma unroll
            for (int p = 0; p < 2; p++) {
                int c = warp_n * 32 + p * 16 + q * 4;
                int nA = 2 * p, nB = 2 * p + 1;
                if (row0 < NN) {
                    float4 hv = *(const float4*)(h + (size_t)row0 * 128 + c);
                    *(float4*)(out + (size_t)row0 * 128 + c) =
                        make_float4(hv.x + acc[mt][nA][0] + bv[p].x,
                                    hv.y + acc[mt][nA][1] + bv[p].y,
                                    hv.z + acc[mt][nB][0] + bv[p].z,
                                    hv.w + acc[mt][nB][1] + bv[p].w);
                }
                if (row0 + 8 < NN) {
                    float4 hv = *(const float4*)(h + (size_t)(row0 + 8) * 128 + c);
                    *(float4*)(out + (size_t)(row0 + 8) * 128 + c) =
                        make_float4(hv.x + acc[mt][nA][2] + bv[p].x,
                                    hv.y + acc[mt][nA][3] + bv[p].y,
                                    hv.z + acc[mt][nB][2] + bv[p].z,
                                    hv.w + acc[mt][nB][3] + bv[p].w);
                }
            }
        }
    }
}

extern "C" void kernel_launch(void* const* d_in, const int* in_sizes, int n_in,
                              void* d_out, int out_size) {
    (void)in_sizes; (void)n_in; (void)out_size;
    const float* xz  = (const float*)d_in[0];
    const float* h   = (const float*)d_in[1];
    const float* We1 = (const float*)d_in[2];
    const float* be1 = (const float*)d_in[3];
    const float* We2 = (const float*)d_in[4];
    const float* be2 = (const float*)d_in[5];
    const float* Wn1 = (const float*)d_in[6];
    const float* bn1 = (const float*)d_in[7];
    const float* Wn2 = (const float*)d_in[8];
    const float* bn2 = (const float*)d_in[9];
    const int*   ei  = (const int*)d_in[10];
    float* out = (float*)d_out;

    cudaFuncSetAttribute(k_pre_mma,   cudaFuncAttributeMaxDynamicSharedMemorySize, 196608);
    cudaFuncSetAttribute(k_edge4,     cudaFuncAttributeMaxDynamicSharedMemorySize, 82944);
    cudaFuncSetAttribute(k_node1_mma, cudaFuncAttributeMaxDynamicSharedMemorySize, 196608);
    cudaFuncSetAttribute(k_node2_mma, cudaFuncAttributeMaxDynamicSharedMemorySize, 131072);

    k_zero<<<1024, 256>>>();
    k_deg<<<1024, 256>>>(ei);
    k_bsum<<<NBLK, 256>>>();
    k_sscan<<<1, 256>>>();
    k_wcur<<<NBLK, 256>>>();
    k_scatter<<<1024, 256>>>(ei);
    k_pre_mma<<<152, 512, 196608>>>(h, We1);
    k_edge4<<<304, 256, 82944>>>(xz, We1, be1, We2, be2);
    k_node1_mma<<<152, 512, 196608>>>(h, Wn1, bn1);
    k_node2_mma<<<152, 512, 131072>>>(h, Wn2, bn2, out);
}